// round 2
// baseline (speedup 1.0000x reference)
#include <cuda_runtime.h>
#include <cuda_fp16.h>
#include <cstdint>
#include <math.h>

// ============================================================
// Problem constants
// ============================================================
#define B_ROWS 8192
#define D_DIM  1024
#define K_CB   4096
#define L_STEPS 8
#define RES_TH 1e-3f

// GEMM tiling
#define BM 128
#define BN 128
#define BK 64
#define NT    (K_CB / BN)     // 32 N-tiles
#define NKCH  (D_DIM / BK)    // 16 K-chunks

// smem: 4 planes (A0,A1,B0,B1), each BM(or BN) x BK halves = 16KB
#define PLANE_BYTES (128 * BK * 2)            // 16384
#define STAGE_BYTES (4 * PLANE_BYTES)          // 65536
#define SMEM_TOTAL  (2 * STAGE_BYTES)          // 131072

// ============================================================
// Device scratch (static __device__ arrays: allocation-free)
// ============================================================
__device__ __align__(128) float  g_resid[B_ROWS * D_DIM];
__device__ __align__(128) __half g_rh0[B_ROWS * D_DIM];
__device__ __align__(128) __half g_rh1[B_ROWS * D_DIM];
__device__ __align__(128) __half g_cb0[K_CB * D_DIM];
__device__ __align__(128) __half g_cb1[K_CB * D_DIM];
__device__ float g_pmax[B_ROWS * NT];
__device__ int   g_pidx[B_ROWS * NT];
__device__ float g_norm2[B_ROWS];
__device__ int   g_active[B_ROWS];
__device__ int   g_indices[B_ROWS * L_STEPS];

// ============================================================
// PTX helpers (sm_100 baseline ISA: cp.async + ldmatrix + mma.sync)
// ============================================================
__device__ __forceinline__ uint32_t smem_u32(const void* p) {
    uint32_t a;
    asm("{ .reg .u64 t; cvta.to.shared.u64 t, %1; cvt.u32.u64 %0, t; }"
        : "=r"(a) : "l"(p));
    return a;
}

__device__ __forceinline__ void cp16(uint32_t s, const void* g) {
    asm volatile("cp.async.cg.shared.global [%0], [%1], 16;" :: "r"(s), "l"(g));
}
#define CP_COMMIT() asm volatile("cp.async.commit_group;" ::: "memory")
#define CP_WAIT(n)  asm volatile("cp.async.wait_group %0;" :: "n"(n) : "memory")

__device__ __forceinline__ void ldsm4(uint32_t* r, uint32_t addr) {
    asm volatile("ldmatrix.sync.aligned.m8n8.x4.shared.b16 {%0,%1,%2,%3}, [%4];"
        : "=r"(r[0]), "=r"(r[1]), "=r"(r[2]), "=r"(r[3]) : "r"(addr));
}

__device__ __forceinline__ void mma16816(float* c, const uint32_t* a, const uint32_t* b) {
    asm volatile(
        "mma.sync.aligned.m16n8k16.row.col.f32.f16.f16.f32 "
        "{%0,%1,%2,%3}, {%4,%5,%6,%7}, {%8,%9}, {%0,%1,%2,%3};"
        : "+f"(c[0]), "+f"(c[1]), "+f"(c[2]), "+f"(c[3])
        : "r"(a[0]), "r"(a[1]), "r"(a[2]), "r"(a[3]), "r"(b[0]), "r"(b[1]));
}

// Swizzle<3,3,3>: 8 x 16B units per 128B row; phys unit = unit ^ (row & 7)
__device__ __forceinline__ uint32_t sw_addr(uint32_t base, int row, int unit) {
    return base + (uint32_t)(row * 128) + (uint32_t)((unit ^ (row & 7)) << 4);
}

// ============================================================
// GEMM + fused argmax partials
// grid: (B_ROWS/BM, K_CB/BN), 256 threads (8 warps: warpM = w>>2, warpN = w&3)
// warp tile 64 (M) x 32 (N)
// ============================================================
__device__ __forceinline__ void fill_stage(uint32_t st, int tileM, int tileN,
                                           int kc, int tid) {
    const __half* a0 = g_rh0 + ((size_t)tileM * BM) * D_DIM + kc * BK;
    const __half* a1 = g_rh1 + ((size_t)tileM * BM) * D_DIM + kc * BK;
    const __half* b0 = g_cb0 + ((size_t)tileN * BN) * D_DIM + kc * BK;
    const __half* b1 = g_cb1 + ((size_t)tileN * BN) * D_DIM + kc * BK;
    // per plane: 128 rows x 8 units(16B) = 1024 chunks; 256 threads -> 4 iters
    #pragma unroll
    for (int i = 0; i < 4; i++) {
        int c = tid + i * 256;
        int row = c >> 3, u = c & 7;
        uint32_t sw = (uint32_t)(row * 128) + (uint32_t)((u ^ (row & 7)) << 4);
        size_t go = (size_t)row * D_DIM + (u << 3);
        cp16(st + 0 * PLANE_BYTES + sw, a0 + go);
        cp16(st + 1 * PLANE_BYTES + sw, a1 + go);
        cp16(st + 2 * PLANE_BYTES + sw, b0 + go);
        cp16(st + 3 * PLANE_BYTES + sw, b1 + go);
    }
}

__global__ void __launch_bounds__(256, 1) gemm_argmax_kernel() {
    extern __shared__ char smem[];
    uint32_t sb = smem_u32(smem);
    const int tid = threadIdx.x;
    const int tileM = blockIdx.x, tileN = blockIdx.y;
    const int wid = tid >> 5, lane = tid & 31;
    const int warpM = wid >> 2, warpN = wid & 3;
    const int grp = lane >> 2, qc = lane & 3;

    float acc[4][4][4];
    #pragma unroll
    for (int mi = 0; mi < 4; mi++)
        #pragma unroll
        for (int ni = 0; ni < 4; ni++)
            #pragma unroll
            for (int j = 0; j < 4; j++) acc[mi][ni][j] = 0.f;

    // prologue
    fill_stage(sb, tileM, tileN, 0, tid);
    CP_COMMIT();

    for (int kc = 0; kc < NKCH; kc++) {
        uint32_t st = sb + (uint32_t)((kc & 1) * STAGE_BYTES);
        if (kc + 1 < NKCH) {
            fill_stage(sb + (uint32_t)(((kc + 1) & 1) * STAGE_BYTES),
                       tileM, tileN, kc + 1, tid);
            CP_COMMIT();
            CP_WAIT(1);
        } else {
            CP_WAIT(0);
        }
        __syncthreads();

        uint32_t aBase0 = st + 0 * PLANE_BYTES;
        uint32_t aBase1 = st + 1 * PLANE_BYTES;
        uint32_t bBase0 = st + 2 * PLANE_BYTES;
        uint32_t bBase1 = st + 3 * PLANE_BYTES;

        #pragma unroll
        for (int ks = 0; ks < 4; ks++) {
            const int u = ks * 2;
            // fragment addresses
            const int aRow = warpM * 64 + (lane & 15);
            const int aU   = u + (lane >> 4);
            const int bRow = warpN * 32 + ((lane >> 4) << 3) + (lane & 7);
            const int bU   = u + ((lane >> 3) & 1);

            uint32_t a0f[4][4], a1f[4][4], b0f[4][2], b1f[4][2];
            #pragma unroll
            for (int mi = 0; mi < 4; mi++)
                ldsm4(a0f[mi], sw_addr(aBase0, aRow + mi * 16, aU));
            #pragma unroll
            for (int nb = 0; nb < 2; nb++) {
                uint32_t r[4];
                ldsm4(r, sw_addr(bBase0, bRow + nb * 16, bU));
                b0f[nb * 2 + 0][0] = r[0]; b0f[nb * 2 + 0][1] = r[1];
                b0f[nb * 2 + 1][0] = r[2]; b0f[nb * 2 + 1][1] = r[3];
            }
            #pragma unroll
            for (int mi = 0; mi < 4; mi++)
                #pragma unroll
                for (int ni = 0; ni < 4; ni++)
                    mma16816(acc[mi][ni], a0f[mi], b0f[ni]);

            #pragma unroll
            for (int nb = 0; nb < 2; nb++) {
                uint32_t r[4];
                ldsm4(r, sw_addr(bBase1, bRow + nb * 16, bU));
                b1f[nb * 2 + 0][0] = r[0]; b1f[nb * 2 + 0][1] = r[1];
                b1f[nb * 2 + 1][0] = r[2]; b1f[nb * 2 + 1][1] = r[3];
            }
            #pragma unroll
            for (int mi = 0; mi < 4; mi++)
                #pragma unroll
                for (int ni = 0; ni < 4; ni++)
                    mma16816(acc[mi][ni], a0f[mi], b1f[ni]);

            #pragma unroll
            for (int mi = 0; mi < 4; mi++)
                ldsm4(a1f[mi], sw_addr(aBase1, aRow + mi * 16, aU));
            #pragma unroll
            for (int mi = 0; mi < 4; mi++)
                #pragma unroll
                for (int ni = 0; ni < 4; ni++)
                    mma16816(acc[mi][ni], a1f[mi], b0f[ni]);
        }
        __syncthreads();
    }

    // ---------------- epilogue: fused argmax ----------------
    // reuse smem: vals[128][4], idxs[128][4]
    float* sval = (float*)smem;
    int*   sidx = (int*)(smem + 128 * 4 * sizeof(float));

    #pragma unroll
    for (int mi = 0; mi < 4; mi++) {
        float bvLo = -3.4e38f, bvHi = -3.4e38f;
        int biLo = 0, biHi = 0;
        #pragma unroll
        for (int ni = 0; ni < 4; ni++) {
            #pragma unroll
            for (int j = 0; j < 2; j++) {
                int c = warpN * 32 + ni * 8 + qc * 2 + j;
                float vLo = acc[mi][ni][j];
                float vHi = acc[mi][ni][2 + j];
                if (vLo > bvLo) { bvLo = vLo; biLo = c; }
                if (vHi > bvHi) { bvHi = vHi; biHi = c; }
            }
        }
        // quad reduce (lanes sharing same row), prefer lower index on tie
        #pragma unroll
        for (int off = 1; off < 4; off <<= 1) {
            float ovLo = __shfl_xor_sync(0xffffffffu, bvLo, off);
            int   oiLo = __shfl_xor_sync(0xffffffffu, biLo, off);
            if (ovLo > bvLo || (ovLo == bvLo && oiLo < biLo)) { bvLo = ovLo; biLo = oiLo; }
            float ovHi = __shfl_xor_sync(0xffffffffu, bvHi, off);
            int   oiHi = __shfl_xor_sync(0xffffffffu, biHi, off);
            if (ovHi > bvHi || (ovHi == bvHi && oiHi < biHi)) { bvHi = ovHi; biHi = oiHi; }
        }
        if (qc == 0) {
            int rLo = warpM * 64 + mi * 16 + grp;
            sval[rLo * 4 + warpN] = bvLo;  sidx[rLo * 4 + warpN] = biLo;
            sval[(rLo + 8) * 4 + warpN] = bvHi;  sidx[(rLo + 8) * 4 + warpN] = biHi;
        }
    }
    __syncthreads();

    if (tid < 128) {
        float bv = -3.4e38f; int bi = 0;
        #pragma unroll
        for (int w = 0; w < 4; w++) {     // ascending col ranges
            float v = sval[tid * 4 + w];
            int   i = sidx[tid * 4 + w];
            if (v > bv || (v == bv && i < bi)) { bv = v; bi = i; }
        }
        int row = tileM * BM + tid;
        g_pmax[(size_t)row * NT + tileN] = bv;
        g_pidx[(size_t)row * NT + tileN] = tileN * BN + bi;
    }
}

// ============================================================
// codebook split (once per launch)
// ============================================================
__global__ void split_cb_kernel(const float* __restrict__ cb) {
    int r = blockIdx.x;
    for (int c = threadIdx.x; c < D_DIM; c += 256) {
        float v = cb[(size_t)r * D_DIM + c];
        __half h0 = __float2half(v);
        __half h1 = __float2half(v - __half2float(h0));
        g_cb0[(size_t)r * D_DIM + c] = h0;
        g_cb1[(size_t)r * D_DIM + c] = h1;
    }
}

// ============================================================
// init: residual = targets, split planes, norm2, active=1
// ============================================================
__global__ void init_kernel(const float* __restrict__ targets) {
    int r = blockIdx.x;
    int tid = threadIdx.x;
    __shared__ float red[256];
    float local = 0.f;
    for (int c = tid; c < D_DIM; c += 256) {
        float v = targets[(size_t)r * D_DIM + c];
        g_resid[(size_t)r * D_DIM + c] = v;
        __half h0 = __float2half(v);
        __half h1 = __float2half(v - __half2float(h0));
        g_rh0[(size_t)r * D_DIM + c] = h0;
        g_rh1[(size_t)r * D_DIM + c] = h1;
        local += v * v;
    }
    red[tid] = local;
    __syncthreads();
    for (int s = 128; s > 0; s >>= 1) {
        if (tid < s) red[tid] += red[tid + s];
        __syncthreads();
    }
    if (tid == 0) {
        g_norm2[r] = red[0];
        g_active[r] = 1;
    }
}

// ============================================================
// reduce partials + update residual for step s
// ============================================================
__global__ void update_kernel(const float* __restrict__ cb, int step, float decay) {
    int r = blockIdx.x;
    int tid = threadIdx.x;
    __shared__ int s_idx, s_act;
    __shared__ float red[256];

    if (tid == 0) {
        float bm = -3.4e38f;
        int bi = 0;
        #pragma unroll
        for (int t = 0; t < NT; t++) {   // ascending tile order => first-max tie-break
            float m = g_pmax[(size_t)r * NT + t];
            if (m > bm) { bm = m; bi = g_pidx[(size_t)r * NT + t]; }
        }
        int act = g_active[r] && (sqrtf(g_norm2[r]) >= RES_TH);
        g_active[r] = act;
        g_indices[(size_t)r * L_STEPS + step] = act ? bi : -1;
        s_idx = bi;
        s_act = act;
    }
    __syncthreads();
    if (!s_act) return;

    int idx = s_idx;
    float local = 0.f;
    for (int c = tid; c < D_DIM; c += 256) {
        float v = g_resid[(size_t)r * D_DIM + c];
        float contr = __fmul_rn(decay, cb[(size_t)idx * D_DIM + c]);
        v = __fsub_rn(v, contr);   // match reference's mul-then-sub rounding
        g_resid[(size_t)r * D_DIM + c] = v;
        __half h0 = __float2half(v);
        __half h1 = __float2half(v - __half2float(h0));
        g_rh0[(size_t)r * D_DIM + c] = h0;
        g_rh1[(size_t)r * D_DIM + c] = h1;
        local += v * v;
    }
    red[tid] = local;
    __syncthreads();
    for (int s2 = 128; s2 > 0; s2 >>= 1) {
        if (tid < s2) red[tid] += red[tid + s2];
        __syncthreads();
    }
    if (tid == 0) g_norm2[r] = red[0];
}

// ============================================================
// finalize variants
// ============================================================
__global__ void out_both_f32(float* __restrict__ out) {
    int r = blockIdx.x;
    for (int c = threadIdx.x; c < D_DIM; c += 256)
        out[(size_t)B_ROWS * L_STEPS + (size_t)r * D_DIM + c] = g_resid[(size_t)r * D_DIM + c];
    if (threadIdx.x < L_STEPS)
        out[(size_t)r * L_STEPS + threadIdx.x] = (float)g_indices[(size_t)r * L_STEPS + threadIdx.x];
}

__global__ void out_idx_i32(int* __restrict__ out) {
    int i = blockIdx.x * 256 + threadIdx.x;
    if (i < B_ROWS * L_STEPS) out[i] = g_indices[i];
}

__global__ void out_res_f32(float* __restrict__ out) {
    int r = blockIdx.x;
    for (int c = threadIdx.x; c < D_DIM; c += 256)
        out[(size_t)r * D_DIM + c] = g_resid[(size_t)r * D_DIM + c];
}

// ============================================================
// host launcher
// ============================================================
extern "C" void kernel_launch(void* const* d_in, const int* in_sizes, int n_in,
                              void* d_out, int out_size) {
    const float* targets  = (const float*)d_in[0];
    const float* codebook = (const float*)d_in[1];

    cudaFuncSetAttribute(gemm_argmax_kernel,
                         cudaFuncAttributeMaxDynamicSharedMemorySize, SMEM_TOTAL);

    split_cb_kernel<<<K_CB, 256>>>(codebook);
    init_kernel<<<B_ROWS, 256>>>(targets);

    for (int s = 0; s < L_STEPS; s++) {
        dim3 grid(B_ROWS / BM, K_CB / BN);
        gemm_argmax_kernel<<<grid, 256, SMEM_TOTAL>>>();
        float decay = (float)pow(0.9, (double)s);
        update_kernel<<<B_ROWS, 256>>>(codebook, s, decay);
    }

    if (out_size == B_ROWS * L_STEPS) {
        out_idx_i32<<<(B_ROWS * L_STEPS + 255) / 256, 256>>>((int*)d_out);
    } else if (out_size == B_ROWS * D_DIM) {
        out_res_f32<<<B_ROWS, 256>>>((float*)d_out);
    } else {
        out_both_f32<<<B_ROWS, 256>>>((float*)d_out);
    }
}

// round 3
// speedup vs baseline: 1.0307x; 1.0307x over previous
#include <cuda_runtime.h>
#include <cuda_fp16.h>
#include <cstdint>
#include <math.h>

// ============================================================
// Problem constants
// ============================================================
#define B_ROWS 8192
#define D_DIM  1024
#define K_CB   4096
#define L_STEPS 8
#define RES_TH 1e-3f

// GEMM tiling
#define BM 128
#define BN 128
#define BK 64
#define NT    (K_CB / BN)     // 32 N-tiles
#define NKCH  (D_DIM / BK)    // 16 K-chunks
#define NSTAGE 3

// smem: 4 planes (A0,A1,B0,B1), each 128 x BK halves = 16KB
#define PLANE_BYTES (128 * BK * 2)            // 16384
#define STAGE_BYTES (4 * PLANE_BYTES)          // 65536
#define SMEM_TOTAL  (NSTAGE * STAGE_BYTES)     // 196608

// ============================================================
// Device scratch
// ============================================================
__device__ __align__(128) float  g_resid[B_ROWS * D_DIM];
__device__ __align__(128) __half g_rh0[B_ROWS * D_DIM];
__device__ __align__(128) __half g_rh1[B_ROWS * D_DIM];
__device__ __align__(128) __half g_cb0[K_CB * D_DIM];
__device__ __align__(128) __half g_cb1[K_CB * D_DIM];
__device__ float g_pmax[B_ROWS * NT];
__device__ int   g_pidx[B_ROWS * NT];
__device__ float g_norm2[B_ROWS];
__device__ int   g_active[B_ROWS];
__device__ int   g_indices[B_ROWS * L_STEPS];

// ============================================================
// PTX helpers
// ============================================================
__device__ __forceinline__ uint32_t smem_u32(const void* p) {
    uint32_t a;
    asm("{ .reg .u64 t; cvta.to.shared.u64 t, %1; cvt.u32.u64 %0, t; }"
        : "=r"(a) : "l"(p));
    return a;
}

__device__ __forceinline__ void cp16(uint32_t s, const void* g) {
    asm volatile("cp.async.cg.shared.global [%0], [%1], 16;" :: "r"(s), "l"(g));
}
#define CP_COMMIT() asm volatile("cp.async.commit_group;" ::: "memory")
#define CP_WAIT(n)  asm volatile("cp.async.wait_group %0;" :: "n"(n) : "memory")

__device__ __forceinline__ void ldsm4(uint32_t* r, uint32_t addr) {
    asm volatile("ldmatrix.sync.aligned.m8n8.x4.shared.b16 {%0,%1,%2,%3}, [%4];"
        : "=r"(r[0]), "=r"(r[1]), "=r"(r[2]), "=r"(r[3]) : "r"(addr));
}

__device__ __forceinline__ void mma16816(float* c, const uint32_t* a, const uint32_t* b) {
    asm volatile(
        "mma.sync.aligned.m16n8k16.row.col.f32.f16.f16.f32 "
        "{%0,%1,%2,%3}, {%4,%5,%6,%7}, {%8,%9}, {%0,%1,%2,%3};"
        : "+f"(c[0]), "+f"(c[1]), "+f"(c[2]), "+f"(c[3])
        : "r"(a[0]), "r"(a[1]), "r"(a[2]), "r"(a[3]), "r"(b[0]), "r"(b[1]));
}

// Swizzle<3,3,3>: phys unit = unit ^ (row & 7), 8 x 16B units per 128B row
__device__ __forceinline__ uint32_t sw_addr(uint32_t base, int row, int unit) {
    return base + (uint32_t)(row * 128) + (uint32_t)((unit ^ (row & 7)) << 4);
}

// ============================================================
// GEMM + fused argmax partials
// grid: (B_ROWS/BM, K_CB/BN), 256 threads, warp tile 64x32
// ============================================================
__device__ __forceinline__ void fill_stage(uint32_t st, int tileM, int tileN,
                                           int kc, int tid) {
    const __half* a0 = g_rh0 + ((size_t)tileM * BM) * D_DIM + kc * BK;
    const __half* a1 = g_rh1 + ((size_t)tileM * BM) * D_DIM + kc * BK;
    const __half* b0 = g_cb0 + ((size_t)tileN * BN) * D_DIM + kc * BK;
    const __half* b1 = g_cb1 + ((size_t)tileN * BN) * D_DIM + kc * BK;
    #pragma unroll
    for (int i = 0; i < 4; i++) {
        int c = tid + i * 256;
        int row = c >> 3, u = c & 7;
        uint32_t sw = (uint32_t)(row * 128) + (uint32_t)((u ^ (row & 7)) << 4);
        size_t go = (size_t)row * D_DIM + (u << 3);
        cp16(st + 0 * PLANE_BYTES + sw, a0 + go);
        cp16(st + 1 * PLANE_BYTES + sw, a1 + go);
        cp16(st + 2 * PLANE_BYTES + sw, b0 + go);
        cp16(st + 3 * PLANE_BYTES + sw, b1 + go);
    }
}

__global__ void __launch_bounds__(256, 1) gemm_argmax_kernel() {
    extern __shared__ char smem[];
    uint32_t sb = smem_u32(smem);
    const int tid = threadIdx.x;
    const int tileM = blockIdx.x, tileN = blockIdx.y;
    const int wid = tid >> 5, lane = tid & 31;
    const int warpM = wid >> 2, warpN = wid & 3;
    const int grp = lane >> 2, qc = lane & 3;

    float acc[4][4][4];
    #pragma unroll
    for (int mi = 0; mi < 4; mi++)
        #pragma unroll
        for (int ni = 0; ni < 4; ni++)
            #pragma unroll
            for (int j = 0; j < 4; j++) acc[mi][ni][j] = 0.f;

    // prologue: fill stages 0 and 1
    fill_stage(sb, tileM, tileN, 0, tid);
    CP_COMMIT();
    fill_stage(sb + STAGE_BYTES, tileM, tileN, 1, tid);
    CP_COMMIT();

    #pragma unroll 1
    for (int kc = 0; kc < NKCH; kc++) {
        // wait for oldest in-flight group (stage kc)
        if (kc + 1 < NKCH) { CP_WAIT(1); } else { CP_WAIT(0); }
        __syncthreads();  // also guarantees compute on stage (kc-1) finished

        // prefetch chunk kc+2 into stage (kc+2)%3 (reuses stage (kc-1)%3)
        if (kc + 2 < NKCH) {
            fill_stage(sb + (uint32_t)(((kc + 2) % NSTAGE) * STAGE_BYTES),
                       tileM, tileN, kc + 2, tid);
            CP_COMMIT();
        }

        uint32_t st = sb + (uint32_t)((kc % NSTAGE) * STAGE_BYTES);
        uint32_t aBase0 = st + 0 * PLANE_BYTES;
        uint32_t aBase1 = st + 1 * PLANE_BYTES;
        uint32_t bBase0 = st + 2 * PLANE_BYTES;
        uint32_t bBase1 = st + 3 * PLANE_BYTES;

        const int aRowB = warpM * 64 + (lane & 15);
        const int bRowB = warpN * 32 + ((lane >> 4) << 3) + (lane & 7);

        #pragma unroll
        for (int ks = 0; ks < 4; ks++) {
            const int u = ks * 2;
            const int aU = u + (lane >> 4);
            const int bU = u + ((lane >> 3) & 1);

            uint32_t a0f[4][4], a1f[4][4], b0f[4][2], b1f[4][2];
            #pragma unroll
            for (int mi = 0; mi < 4; mi++)
                ldsm4(a0f[mi], sw_addr(aBase0, aRowB + mi * 16, aU));
            #pragma unroll
            for (int nb = 0; nb < 2; nb++) {
                uint32_t r[4];
                ldsm4(r, sw_addr(bBase0, bRowB + nb * 16, bU));
                b0f[nb * 2 + 0][0] = r[0]; b0f[nb * 2 + 0][1] = r[1];
                b0f[nb * 2 + 1][0] = r[2]; b0f[nb * 2 + 1][1] = r[3];
            }
            #pragma unroll
            for (int mi = 0; mi < 4; mi++)
                #pragma unroll
                for (int ni = 0; ni < 4; ni++)
                    mma16816(acc[mi][ni], a0f[mi], b0f[ni]);

            #pragma unroll
            for (int nb = 0; nb < 2; nb++) {
                uint32_t r[4];
                ldsm4(r, sw_addr(bBase1, bRowB + nb * 16, bU));
                b1f[nb * 2 + 0][0] = r[0]; b1f[nb * 2 + 0][1] = r[1];
                b1f[nb * 2 + 1][0] = r[2]; b1f[nb * 2 + 1][1] = r[3];
            }
            #pragma unroll
            for (int mi = 0; mi < 4; mi++)
                #pragma unroll
                for (int ni = 0; ni < 4; ni++)
                    mma16816(acc[mi][ni], a0f[mi], b1f[ni]);

            #pragma unroll
            for (int mi = 0; mi < 4; mi++)
                ldsm4(a1f[mi], sw_addr(aBase1, aRowB + mi * 16, aU));
            #pragma unroll
            for (int mi = 0; mi < 4; mi++)
                #pragma unroll
                for (int ni = 0; ni < 4; ni++)
                    mma16816(acc[mi][ni], a1f[mi], b0f[ni]);
        }
    }

    __syncthreads();  // all compute done before epilogue reuses smem

    // ---------------- epilogue: fused argmax ----------------
    float* sval = (float*)smem;
    int*   sidx = (int*)(smem + 128 * 4 * sizeof(float));

    #pragma unroll
    for (int mi = 0; mi < 4; mi++) {
        float bvLo = -3.4e38f, bvHi = -3.4e38f;
        int biLo = 0, biHi = 0;
        #pragma unroll
        for (int ni = 0; ni < 4; ni++) {
            #pragma unroll
            for (int j = 0; j < 2; j++) {
                int c = warpN * 32 + ni * 8 + qc * 2 + j;
                float vLo = acc[mi][ni][j];
                float vHi = acc[mi][ni][2 + j];
                if (vLo > bvLo) { bvLo = vLo; biLo = c; }
                if (vHi > bvHi) { bvHi = vHi; biHi = c; }
            }
        }
        #pragma unroll
        for (int off = 1; off < 4; off <<= 1) {
            float ovLo = __shfl_xor_sync(0xffffffffu, bvLo, off);
            int   oiLo = __shfl_xor_sync(0xffffffffu, biLo, off);
            if (ovLo > bvLo || (ovLo == bvLo && oiLo < biLo)) { bvLo = ovLo; biLo = oiLo; }
            float ovHi = __shfl_xor_sync(0xffffffffu, bvHi, off);
            int   oiHi = __shfl_xor_sync(0xffffffffu, biHi, off);
            if (ovHi > bvHi || (ovHi == bvHi && oiHi < biHi)) { bvHi = ovHi; biHi = oiHi; }
        }
        if (qc == 0) {
            int rLo = warpM * 64 + mi * 16 + grp;
            sval[rLo * 4 + warpN] = bvLo;  sidx[rLo * 4 + warpN] = biLo;
            sval[(rLo + 8) * 4 + warpN] = bvHi;  sidx[(rLo + 8) * 4 + warpN] = biHi;
        }
    }
    __syncthreads();

    if (tid < 128) {
        float bv = -3.4e38f; int bi = 0;
        #pragma unroll
        for (int w = 0; w < 4; w++) {     // ascending col ranges => first-max wins
            float v = sval[tid * 4 + w];
            int   i = sidx[tid * 4 + w];
            if (v > bv || (v == bv && i < bi)) { bv = v; bi = i; }
        }
        int row = tileM * BM + tid;
        g_pmax[(size_t)row * NT + tileN] = bv;
        g_pidx[(size_t)row * NT + tileN] = tileN * BN + bi;
    }
}

// ============================================================
// codebook split
// ============================================================
__global__ void split_cb_kernel(const float* __restrict__ cb) {
    int r = blockIdx.x;
    for (int c = threadIdx.x; c < D_DIM; c += 256) {
        float v = cb[(size_t)r * D_DIM + c];
        __half h0 = __float2half(v);
        __half h1 = __float2half(v - __half2float(h0));
        g_cb0[(size_t)r * D_DIM + c] = h0;
        g_cb1[(size_t)r * D_DIM + c] = h1;
    }
}

// ============================================================
// init: residual = targets, split planes, norm2, active=1
// ============================================================
__global__ void init_kernel(const float* __restrict__ targets) {
    int r = blockIdx.x;
    int tid = threadIdx.x;       // 256 threads, one float4 each
    int lane = tid & 31, wid = tid >> 5;
    __shared__ float wsum[8];

    const float4* t4 = (const float4*)(targets + (size_t)r * D_DIM);
    float4* r4 = (float4*)(g_resid + (size_t)r * D_DIM);
    __half2* h0p = (__half2*)(g_rh0 + (size_t)r * D_DIM);
    __half2* h1p = (__half2*)(g_rh1 + (size_t)r * D_DIM);

    float4 v = t4[tid];
    r4[tid] = v;
    float2 lo = make_float2(v.x, v.y), hi = make_float2(v.z, v.w);
    __half2 h0lo = __float22half2_rn(lo);
    __half2 h0hi = __float22half2_rn(hi);
    float2 e_lo = make_float2(lo.x - __low2float(h0lo), lo.y - __high2float(h0lo));
    float2 e_hi = make_float2(hi.x - __low2float(h0hi), hi.y - __high2float(h0hi));
    h0p[tid * 2 + 0] = h0lo;  h0p[tid * 2 + 1] = h0hi;
    h1p[tid * 2 + 0] = __float22half2_rn(e_lo);
    h1p[tid * 2 + 1] = __float22half2_rn(e_hi);

    float local = v.x * v.x + v.y * v.y + v.z * v.z + v.w * v.w;
    #pragma unroll
    for (int off = 16; off > 0; off >>= 1)
        local += __shfl_xor_sync(0xffffffffu, local, off);
    if (lane == 0) wsum[wid] = local;
    __syncthreads();
    if (tid == 0) {
        float s = 0.f;
        #pragma unroll
        for (int w = 0; w < 8; w++) s += wsum[w];
        g_norm2[r] = s;
        g_active[r] = 1;
    }
}

// ============================================================
// reduce partials + update residual for step s
// ============================================================
__global__ void update_kernel(const float* __restrict__ cb, int step, float decay) {
    int r = blockIdx.x;
    int tid = threadIdx.x;       // 256 threads
    int lane = tid & 31, wid = tid >> 5;
    __shared__ int s_idx, s_act;
    __shared__ float wsum[8];

    if (wid == 0) {
        // parallel (max, min-idx-on-tie) reduce over 32 partials — semilattice,
        // butterfly-safe
        float v = g_pmax[(size_t)r * NT + lane];
        int   i = g_pidx[(size_t)r * NT + lane];
        #pragma unroll
        for (int off = 16; off > 0; off >>= 1) {
            float ov = __shfl_xor_sync(0xffffffffu, v, off);
            int   oi = __shfl_xor_sync(0xffffffffu, i, off);
            if (ov > v || (ov == v && oi < i)) { v = ov; i = oi; }
        }
        if (lane == 0) {
            int act = g_active[r] && (sqrtf(g_norm2[r]) >= RES_TH);
            g_active[r] = act;
            g_indices[(size_t)r * L_STEPS + step] = act ? i : -1;
            s_idx = i;
            s_act = act;
        }
    }
    __syncthreads();
    if (!s_act) return;

    int idx = s_idx;
    float4* r4 = (float4*)(g_resid + (size_t)r * D_DIM);
    const float4* c4 = (const float4*)(cb + (size_t)idx * D_DIM);
    __half2* h0p = (__half2*)(g_rh0 + (size_t)r * D_DIM);
    __half2* h1p = (__half2*)(g_rh1 + (size_t)r * D_DIM);

    float4 v = r4[tid];
    float4 c = c4[tid];
    // match reference rounding: fp32 mul then fp32 sub
    v.x = __fsub_rn(v.x, __fmul_rn(decay, c.x));
    v.y = __fsub_rn(v.y, __fmul_rn(decay, c.y));
    v.z = __fsub_rn(v.z, __fmul_rn(decay, c.z));
    v.w = __fsub_rn(v.w, __fmul_rn(decay, c.w));
    r4[tid] = v;

    float2 lo = make_float2(v.x, v.y), hi = make_float2(v.z, v.w);
    __half2 h0lo = __float22half2_rn(lo);
    __half2 h0hi = __float22half2_rn(hi);
    float2 e_lo = make_float2(lo.x - __low2float(h0lo), lo.y - __high2float(h0lo));
    float2 e_hi = make_float2(hi.x - __low2float(h0hi), hi.y - __high2float(h0hi));
    h0p[tid * 2 + 0] = h0lo;  h0p[tid * 2 + 1] = h0hi;
    h1p[tid * 2 + 0] = __float22half2_rn(e_lo);
    h1p[tid * 2 + 1] = __float22half2_rn(e_hi);

    float local = v.x * v.x + v.y * v.y + v.z * v.z + v.w * v.w;
    #pragma unroll
    for (int off = 16; off > 0; off >>= 1)
        local += __shfl_xor_sync(0xffffffffu, local, off);
    if (lane == 0) wsum[wid] = local;
    __syncthreads();
    if (tid == 0) {
        float s = 0.f;
        #pragma unroll
        for (int w = 0; w < 8; w++) s += wsum[w];
        g_norm2[r] = s;
    }
}

// ============================================================
// finalize variants
// ============================================================
__global__ void out_both_f32(float* __restrict__ out) {
    int r = blockIdx.x;
    for (int c = threadIdx.x; c < D_DIM; c += 256)
        out[(size_t)B_ROWS * L_STEPS + (size_t)r * D_DIM + c] = g_resid[(size_t)r * D_DIM + c];
    if (threadIdx.x < L_STEPS)
        out[(size_t)r * L_STEPS + threadIdx.x] = (float)g_indices[(size_t)r * L_STEPS + threadIdx.x];
}

__global__ void out_idx_i32(int* __restrict__ out) {
    int i = blockIdx.x * 256 + threadIdx.x;
    if (i < B_ROWS * L_STEPS) out[i] = g_indices[i];
}

__global__ void out_res_f32(float* __restrict__ out) {
    int r = blockIdx.x;
    for (int c = threadIdx.x; c < D_DIM; c += 256)
        out[(size_t)r * D_DIM + c] = g_resid[(size_t)r * D_DIM + c];
}

// ============================================================
// host launcher
// ============================================================
extern "C" void kernel_launch(void* const* d_in, const int* in_sizes, int n_in,
                              void* d_out, int out_size) {
    const float* targets  = (const float*)d_in[0];
    const float* codebook = (const float*)d_in[1];

    cudaFuncSetAttribute(gemm_argmax_kernel,
                         cudaFuncAttributeMaxDynamicSharedMemorySize, SMEM_TOTAL);

    split_cb_kernel<<<K_CB, 256>>>(codebook);
    init_kernel<<<B_ROWS, 256>>>(targets);

    for (int s = 0; s < L_STEPS; s++) {
        dim3 grid(B_ROWS / BM, K_CB / BN);
        gemm_argmax_kernel<<<grid, 256, SMEM_TOTAL>>>();
        float decay = (float)pow(0.9, (double)s);
        update_kernel<<<B_ROWS, 256>>>(codebook, s, decay);
    }

    if (out_size == B_ROWS * L_STEPS) {
        out_idx_i32<<<(B_ROWS * L_STEPS + 255) / 256, 256>>>((int*)d_out);
    } else if (out_size == B_ROWS * D_DIM) {
        out_res_f32<<<B_ROWS, 256>>>((float*)d_out);
    } else {
        out_both_f32<<<B_ROWS, 256>>>((float*)d_out);
    }
}

// round 4
// speedup vs baseline: 1.3732x; 1.3322x over previous
#include <cuda_runtime.h>
#include <cuda_fp16.h>
#include <cstdint>
#include <math.h>

// ============================================================
// Problem constants
// ============================================================
#define B_ROWS 8192
#define D_DIM  1024
#define K_CB   4096
#define L_STEPS 8
#define RES_TH 1e-3f
#define THR    0.30f

// GEMM tiling
#define BM 128
#define BN 128
#define BK 64
#define NT    (K_CB / BN)     // 32 N-tiles
#define NKCH  (D_DIM / BK)    // 16 K-chunks
#define NSTAGE 4

// smem: 2 planes (A0,B0), each 128 x BK halves = 16KB
#define PLANE_BYTES (128 * BK * 2)            // 16384
#define STAGE_BYTES (2 * PLANE_BYTES)          // 32768
#define SMEM_TOTAL  (NSTAGE * STAGE_BYTES)     // 131072

// ============================================================
// Device scratch
// ============================================================
__device__ __align__(128) float  g_resid[B_ROWS * D_DIM];
__device__ __align__(128) __half g_rh0[B_ROWS * D_DIM];
__device__ __align__(128) __half g_cb0[K_CB * D_DIM];
__device__ float g_t1v[B_ROWS * NT];
__device__ int   g_t1i[B_ROWS * NT];
__device__ float g_t2v[B_ROWS * NT];
__device__ int   g_t2i[B_ROWS * NT];
__device__ float g_norm2[B_ROWS];
__device__ int   g_active[B_ROWS];
__device__ int   g_indices[B_ROWS * L_STEPS];
__device__ int   g_choice[B_ROWS];
__device__ int   g_flagcnt;
__device__ int   g_flaglist[B_ROWS];

// ============================================================
// PTX helpers
// ============================================================
__device__ __forceinline__ uint32_t smem_u32(const void* p) {
    uint32_t a;
    asm("{ .reg .u64 t; cvta.to.shared.u64 t, %1; cvt.u32.u64 %0, t; }"
        : "=r"(a) : "l"(p));
    return a;
}
__device__ __forceinline__ void cp16(uint32_t s, const void* g) {
    asm volatile("cp.async.cg.shared.global [%0], [%1], 16;" :: "r"(s), "l"(g));
}
#define CP_COMMIT() asm volatile("cp.async.commit_group;" ::: "memory")
#define CP_WAIT(n)  asm volatile("cp.async.wait_group %0;" :: "n"(n) : "memory")

__device__ __forceinline__ void ldsm4(uint32_t* r, uint32_t addr) {
    asm volatile("ldmatrix.sync.aligned.m8n8.x4.shared.b16 {%0,%1,%2,%3}, [%4];"
        : "=r"(r[0]), "=r"(r[1]), "=r"(r[2]), "=r"(r[3]) : "r"(addr));
}
__device__ __forceinline__ void mma16816(float* c, const uint32_t* a, const uint32_t* b) {
    asm volatile(
        "mma.sync.aligned.m16n8k16.row.col.f32.f16.f16.f32 "
        "{%0,%1,%2,%3}, {%4,%5,%6,%7}, {%8,%9}, {%0,%1,%2,%3};"
        : "+f"(c[0]), "+f"(c[1]), "+f"(c[2]), "+f"(c[3])
        : "r"(a[0]), "r"(a[1]), "r"(a[2]), "r"(a[3]), "r"(b[0]), "r"(b[1]));
}
__device__ __forceinline__ uint32_t sw_addr(uint32_t base, int row, int unit) {
    return base + (uint32_t)(row * 128) + (uint32_t)((unit ^ (row & 7)) << 4);
}

// top-2 tuple helpers (ties -> lower index)
struct Top2 { float v1; int i1; float v2; int i2; };
__device__ __forceinline__ void t2_insert(Top2& t, float v, int c) {
    if (v > t.v1 || (v == t.v1 && c < t.i1)) {
        t.v2 = t.v1; t.i2 = t.i1; t.v1 = v; t.i1 = c;
    } else if (v > t.v2 || (v == t.v2 && c < t.i2)) {
        t.v2 = v; t.i2 = c;
    }
}
__device__ __forceinline__ void t2_merge(Top2& a, const Top2& b) {
    if (b.v1 > a.v1 || (b.v1 == a.v1 && b.i1 < a.i1)) {
        // b wins; second = better of old (a.v1) and b.v2
        if (a.v1 > b.v2 || (a.v1 == b.v2 && a.i1 < b.i2)) { a.v2 = a.v1; a.i2 = a.i1; }
        else { a.v2 = b.v2; a.i2 = b.i2; }
        a.v1 = b.v1; a.i1 = b.i1;
    } else {
        if (b.v1 > a.v2 || (b.v1 == a.v2 && b.i1 < a.i2)) { a.v2 = b.v1; a.i2 = b.i1; }
    }
}

// ============================================================
// GEMM (single fp16 plane) + fused per-tile top-2
// grid: (64, 32), 256 threads, warp tile 64x32
// ============================================================
__device__ __forceinline__ void fill_stage(uint32_t st, int tileM, int tileN,
                                           int kc, int tid) {
    const __half* a0 = g_rh0 + ((size_t)tileM * BM) * D_DIM + kc * BK;
    const __half* b0 = g_cb0 + ((size_t)tileN * BN) * D_DIM + kc * BK;
    #pragma unroll
    for (int i = 0; i < 4; i++) {
        int c = tid + i * 256;
        int row = c >> 3, u = c & 7;
        uint32_t sw = (uint32_t)(row * 128) + (uint32_t)((u ^ (row & 7)) << 4);
        size_t go = (size_t)row * D_DIM + (u << 3);
        cp16(st + sw, a0 + go);
        cp16(st + PLANE_BYTES + sw, b0 + go);
    }
}

__global__ void __launch_bounds__(256, 1) gemm_argmax_kernel() {
    extern __shared__ char smem[];
    uint32_t sb = smem_u32(smem);
    const int tid = threadIdx.x;
    const int tileM = blockIdx.x, tileN = blockIdx.y;
    const int wid = tid >> 5, lane = tid & 31;
    const int warpM = wid >> 2, warpN = wid & 3;
    const int grp = lane >> 2, qc = lane & 3;

    if (tileM == 0 && tileN == 0 && tid == 0) g_flagcnt = 0;

    float acc[4][4][4];
    #pragma unroll
    for (int mi = 0; mi < 4; mi++)
        #pragma unroll
        for (int ni = 0; ni < 4; ni++)
            #pragma unroll
            for (int j = 0; j < 4; j++) acc[mi][ni][j] = 0.f;

    // prologue: fill stages 0..2
    fill_stage(sb, tileM, tileN, 0, tid);                      CP_COMMIT();
    fill_stage(sb + STAGE_BYTES, tileM, tileN, 1, tid);        CP_COMMIT();
    fill_stage(sb + 2 * STAGE_BYTES, tileM, tileN, 2, tid);    CP_COMMIT();

    #pragma unroll 1
    for (int kc = 0; kc < NKCH; kc++) {
        if (kc < NKCH - 2)      { CP_WAIT(2); }
        else if (kc == NKCH - 2){ CP_WAIT(1); }
        else                    { CP_WAIT(0); }
        __syncthreads();

        if (kc + 3 < NKCH) {
            fill_stage(sb + (uint32_t)(((kc + 3) % NSTAGE) * STAGE_BYTES),
                       tileM, tileN, kc + 3, tid);
            CP_COMMIT();
        }

        uint32_t st = sb + (uint32_t)((kc % NSTAGE) * STAGE_BYTES);
        uint32_t aBase = st;
        uint32_t bBase = st + PLANE_BYTES;
        const int aRowB = warpM * 64 + (lane & 15);
        const int bRowB = warpN * 32 + ((lane >> 4) << 3) + (lane & 7);

        #pragma unroll
        for (int ks = 0; ks < 4; ks++) {
            const int u = ks * 2;
            const int aU = u + (lane >> 4);
            const int bU = u + ((lane >> 3) & 1);

            uint32_t af[4][4], bf[4][2];
            #pragma unroll
            for (int mi = 0; mi < 4; mi++)
                ldsm4(af[mi], sw_addr(aBase, aRowB + mi * 16, aU));
            #pragma unroll
            for (int nb = 0; nb < 2; nb++) {
                uint32_t r[4];
                ldsm4(r, sw_addr(bBase, bRowB + nb * 16, bU));
                bf[nb * 2 + 0][0] = r[0]; bf[nb * 2 + 0][1] = r[1];
                bf[nb * 2 + 1][0] = r[2]; bf[nb * 2 + 1][1] = r[3];
            }
            #pragma unroll
            for (int mi = 0; mi < 4; mi++)
                #pragma unroll
                for (int ni = 0; ni < 4; ni++)
                    mma16816(acc[mi][ni], af[mi], bf[ni]);
        }
    }

    __syncthreads();  // compute done before smem reuse

    // ---------------- epilogue: per-tile top-2 ----------------
    float* sv1 = (float*)smem;                       // [128][4]
    int*   si1 = (int*)(smem + 2048);
    float* sv2 = (float*)(smem + 4096);
    int*   si2 = (int*)(smem + 6144);

    #pragma unroll
    for (int mi = 0; mi < 4; mi++) {
        Top2 lo = {-3.4e38f, 0x7fffffff, -3.4e38f, 0x7fffffff};
        Top2 hi = {-3.4e38f, 0x7fffffff, -3.4e38f, 0x7fffffff};
        #pragma unroll
        for (int ni = 0; ni < 4; ni++) {
            #pragma unroll
            for (int j = 0; j < 2; j++) {
                int c = warpN * 32 + ni * 8 + qc * 2 + j;
                t2_insert(lo, acc[mi][ni][j], c);
                t2_insert(hi, acc[mi][ni][2 + j], c);
            }
        }
        #pragma unroll
        for (int off = 1; off < 4; off <<= 1) {
            Top2 o;
            o.v1 = __shfl_xor_sync(0xffffffffu, lo.v1, off);
            o.i1 = __shfl_xor_sync(0xffffffffu, lo.i1, off);
            o.v2 = __shfl_xor_sync(0xffffffffu, lo.v2, off);
            o.i2 = __shfl_xor_sync(0xffffffffu, lo.i2, off);
            t2_merge(lo, o);
            o.v1 = __shfl_xor_sync(0xffffffffu, hi.v1, off);
            o.i1 = __shfl_xor_sync(0xffffffffu, hi.i1, off);
            o.v2 = __shfl_xor_sync(0xffffffffu, hi.v2, off);
            o.i2 = __shfl_xor_sync(0xffffffffu, hi.i2, off);
            t2_merge(hi, o);
        }
        if (qc == 0) {
            int rLo = warpM * 64 + mi * 16 + grp;
            sv1[rLo * 4 + warpN] = lo.v1;  si1[rLo * 4 + warpN] = lo.i1;
            sv2[rLo * 4 + warpN] = lo.v2;  si2[rLo * 4 + warpN] = lo.i2;
            int rHi = rLo + 8;
            sv1[rHi * 4 + warpN] = hi.v1;  si1[rHi * 4 + warpN] = hi.i1;
            sv2[rHi * 4 + warpN] = hi.v2;  si2[rHi * 4 + warpN] = hi.i2;
        }
    }
    __syncthreads();

    if (tid < 128) {
        Top2 t = {sv1[tid * 4], si1[tid * 4], sv2[tid * 4], si2[tid * 4]};
        #pragma unroll
        for (int w = 1; w < 4; w++) {
            Top2 o = {sv1[tid * 4 + w], si1[tid * 4 + w],
                      sv2[tid * 4 + w], si2[tid * 4 + w]};
            t2_merge(t, o);
        }
        size_t o = (size_t)(tileM * BM + tid) * NT + tileN;
        g_t1v[o] = t.v1;  g_t1i[o] = tileN * BN + t.i1;
        g_t2v[o] = t.v2;  g_t2i[o] = tileN * BN + t.i2;
    }
}

// ============================================================
// select: per-row top-2 merge over 32 tiles, flag near-ties
// grid: 1024 CTAs x 256 thr (8 warps = 8 rows/CTA)
// ============================================================
__global__ void select_kernel() {
    int tid = threadIdx.x, lane = tid & 31, wid = tid >> 5;
    int r = blockIdx.x * 8 + wid;
    size_t o = (size_t)r * NT + lane;
    float v1 = g_t1v[o];
    int   i1 = g_t1i[o];
    float v2 = g_t2v[o];
    #pragma unroll
    for (int off = 16; off > 0; off >>= 1) {
        float ov1 = __shfl_xor_sync(0xffffffffu, v1, off);
        int   oi1 = __shfl_xor_sync(0xffffffffu, i1, off);
        float ov2 = __shfl_xor_sync(0xffffffffu, v2, off);
        if (ov1 > v1 || (ov1 == v1 && oi1 < i1)) {
            v2 = fmaxf(ov2, v1);
            v1 = ov1; i1 = oi1;
        } else {
            v2 = fmaxf(v2, ov1);
        }
    }
    if (lane == 0) {
        g_choice[r] = i1;
        if (v1 - v2 < THR) {
            int p = atomicAdd(&g_flagcnt, 1);
            g_flaglist[p] = r;
        }
    }
}

// ============================================================
// refine: flagged rows -> Kahan fp32 dots on 64 candidates
// grid: 128 CTAs x 256 thr
// ============================================================
__global__ void refine_kernel(const float* __restrict__ cb) {
    __shared__ float sres[D_DIM];
    __shared__ float sv[64];
    __shared__ int   si[64];
    int tid = threadIdx.x, lane = tid & 31, wid = tid >> 5;
    int cnt = *(volatile int*)&g_flagcnt;

    for (int f = blockIdx.x; f < cnt; f += gridDim.x) {
        int r = g_flaglist[f];
        const float4* r4 = (const float4*)(g_resid + (size_t)r * D_DIM);
        ((float4*)sres)[tid] = r4[tid];
        __syncthreads();

        for (int c = wid; c < 64; c += 8) {
            int tile = c >> 1;
            size_t to = (size_t)r * NT + tile;
            int idx = (c & 1) ? g_t2i[to] : g_t1i[to];
            const float* cbr = cb + (size_t)idx * D_DIM;
            float s = 0.f, comp = 0.f;
            for (int e = lane; e < D_DIM; e += 32) {
                float prod = sres[e] * cbr[e];
                float y = prod - comp;
                float t = s + y;
                comp = (t - s) - y;
                s = t;
            }
            #pragma unroll
            for (int off = 16; off > 0; off >>= 1)
                s += __shfl_xor_sync(0xffffffffu, s, off);
            if (lane == 0) { sv[c] = s; si[c] = idx; }
        }
        __syncthreads();
        if (tid == 0) {
            float bv = -3.4e38f; int bi = 0x7fffffff;
            #pragma unroll
            for (int c = 0; c < 64; c++) {
                float v = sv[c]; int i = si[c];
                if (v > bv || (v == bv && i < bi)) { bv = v; bi = i; }
            }
            g_choice[r] = bi;
        }
        __syncthreads();
    }
}

// ============================================================
// init / split
// ============================================================
__global__ void split_cb_kernel(const float* __restrict__ cb) {
    int r = blockIdx.x;
    const float4* c4 = (const float4*)(cb + (size_t)r * D_DIM);
    __half2* h0p = (__half2*)(g_cb0 + (size_t)r * D_DIM);
    int tid = threadIdx.x;
    float4 v = c4[tid];
    h0p[tid * 2 + 0] = __float22half2_rn(make_float2(v.x, v.y));
    h0p[tid * 2 + 1] = __float22half2_rn(make_float2(v.z, v.w));
}

__global__ void init_kernel(const float* __restrict__ targets) {
    int r = blockIdx.x;
    int tid = threadIdx.x;
    int lane = tid & 31, wid = tid >> 5;
    __shared__ float wsum[8];

    const float4* t4 = (const float4*)(targets + (size_t)r * D_DIM);
    float4* r4 = (float4*)(g_resid + (size_t)r * D_DIM);
    __half2* h0p = (__half2*)(g_rh0 + (size_t)r * D_DIM);

    float4 v = t4[tid];
    r4[tid] = v;
    h0p[tid * 2 + 0] = __float22half2_rn(make_float2(v.x, v.y));
    h0p[tid * 2 + 1] = __float22half2_rn(make_float2(v.z, v.w));

    float local = v.x * v.x + v.y * v.y + v.z * v.z + v.w * v.w;
    #pragma unroll
    for (int off = 16; off > 0; off >>= 1)
        local += __shfl_xor_sync(0xffffffffu, local, off);
    if (lane == 0) wsum[wid] = local;
    __syncthreads();
    if (tid == 0) {
        float s = 0.f;
        #pragma unroll
        for (int w = 0; w < 8; w++) s += wsum[w];
        g_norm2[r] = s;
        g_active[r] = 1;
    }
}

// ============================================================
// update residual
// ============================================================
__global__ void update_kernel(const float* __restrict__ cb, int step, float decay) {
    int r = blockIdx.x;
    int tid = threadIdx.x;
    int lane = tid & 31, wid = tid >> 5;
    __shared__ int s_idx, s_act;
    __shared__ float wsum[8];

    if (tid == 0) {
        int i = g_choice[r];
        int act = g_active[r] && (sqrtf(g_norm2[r]) >= RES_TH);
        g_active[r] = act;
        g_indices[(size_t)r * L_STEPS + step] = act ? i : -1;
        s_idx = i;
        s_act = act;
    }
    __syncthreads();
    if (!s_act) return;

    int idx = s_idx;
    float4* r4 = (float4*)(g_resid + (size_t)r * D_DIM);
    const float4* c4 = (const float4*)(cb + (size_t)idx * D_DIM);
    __half2* h0p = (__half2*)(g_rh0 + (size_t)r * D_DIM);

    float4 v = r4[tid];
    float4 c = c4[tid];
    v.x = __fsub_rn(v.x, __fmul_rn(decay, c.x));
    v.y = __fsub_rn(v.y, __fmul_rn(decay, c.y));
    v.z = __fsub_rn(v.z, __fmul_rn(decay, c.z));
    v.w = __fsub_rn(v.w, __fmul_rn(decay, c.w));
    r4[tid] = v;
    h0p[tid * 2 + 0] = __float22half2_rn(make_float2(v.x, v.y));
    h0p[tid * 2 + 1] = __float22half2_rn(make_float2(v.z, v.w));

    float local = v.x * v.x + v.y * v.y + v.z * v.z + v.w * v.w;
    #pragma unroll
    for (int off = 16; off > 0; off >>= 1)
        local += __shfl_xor_sync(0xffffffffu, local, off);
    if (lane == 0) wsum[wid] = local;
    __syncthreads();
    if (tid == 0) {
        float s = 0.f;
        #pragma unroll
        for (int w = 0; w < 8; w++) s += wsum[w];
        g_norm2[r] = s;
    }
}

// ============================================================
// finalize variants
// ============================================================
__global__ void out_both_f32(float* __restrict__ out) {
    int r = blockIdx.x;
    for (int c = threadIdx.x; c < D_DIM; c += 256)
        out[(size_t)B_ROWS * L_STEPS + (size_t)r * D_DIM + c] = g_resid[(size_t)r * D_DIM + c];
    if (threadIdx.x < L_STEPS)
        out[(size_t)r * L_STEPS + threadIdx.x] = (float)g_indices[(size_t)r * L_STEPS + threadIdx.x];
}
__global__ void out_idx_i32(int* __restrict__ out) {
    int i = blockIdx.x * 256 + threadIdx.x;
    if (i < B_ROWS * L_STEPS) out[i] = g_indices[i];
}
__global__ void out_res_f32(float* __restrict__ out) {
    int r = blockIdx.x;
    for (int c = threadIdx.x; c < D_DIM; c += 256)
        out[(size_t)r * D_DIM + c] = g_resid[(size_t)r * D_DIM + c];
}

// ============================================================
// host launcher
// ============================================================
extern "C" void kernel_launch(void* const* d_in, const int* in_sizes, int n_in,
                              void* d_out, int out_size) {
    const float* targets  = (const float*)d_in[0];
    const float* codebook = (const float*)d_in[1];

    cudaFuncSetAttribute(gemm_argmax_kernel,
                         cudaFuncAttributeMaxDynamicSharedMemorySize, SMEM_TOTAL);

    split_cb_kernel<<<K_CB, 256>>>(codebook);
    init_kernel<<<B_ROWS, 256>>>(targets);

    for (int s = 0; s < L_STEPS; s++) {
        dim3 grid(B_ROWS / BM, K_CB / BN);
        gemm_argmax_kernel<<<grid, 256, SMEM_TOTAL>>>();
        select_kernel<<<B_ROWS / 8, 256>>>();
        refine_kernel<<<128, 256>>>(codebook);
        float decay = (float)pow(0.9, (double)s);
        update_kernel<<<B_ROWS, 256>>>(codebook, s, decay);
    }

    if (out_size == B_ROWS * L_STEPS) {
        out_idx_i32<<<(B_ROWS * L_STEPS + 255) / 256, 256>>>((int*)d_out);
    } else if (out_size == B_ROWS * D_DIM) {
        out_res_f32<<<B_ROWS, 256>>>((float*)d_out);
    } else {
        out_both_f32<<<B_ROWS, 256>>>((float*)d_out);
    }
}

// round 5
// speedup vs baseline: 1.5436x; 1.1241x over previous
#include <cuda_runtime.h>
#include <cuda_fp16.h>
#include <cstdint>
#include <math.h>

// ============================================================
// Problem constants
// ============================================================
#define B_ROWS 8192
#define D_DIM  1024
#define K_CB   4096
#define L_STEPS 8
#define RES_TH 1e-3f
#define THR    0.30f

// GEMM tiling: CTA tile 256 (M) x 128 (N), warp tile 64x64
#define BM 256
#define BN 128
#define BK 64
#define NT    (K_CB / BN)     // 32 N-tiles
#define NKCH  (D_DIM / BK)    // 16 K-chunks
#define NSTAGE 4

#define A_BYTES (BM * BK * 2)                 // 32768
#define B_BYTES (BN * BK * 2)                 // 16384
#define STAGE_BYTES (A_BYTES + B_BYTES)       // 49152
#define SMEM_TOTAL  (NSTAGE * STAGE_BYTES)    // 196608

// ============================================================
// Device scratch
// ============================================================
__device__ __align__(128) float  g_resid[B_ROWS * D_DIM];
__device__ __align__(128) __half g_rh0[B_ROWS * D_DIM];
__device__ __align__(128) __half g_cb0[K_CB * D_DIM];
__device__ float g_t1v[B_ROWS * NT];
__device__ int   g_t1i[B_ROWS * NT];
__device__ float g_t2v[B_ROWS * NT];
__device__ int   g_t2i[B_ROWS * NT];
__device__ float g_norm2[B_ROWS];
__device__ int   g_active[B_ROWS];
__device__ int   g_indices[B_ROWS * L_STEPS];
__device__ int   g_choice[B_ROWS];
__device__ int   g_flagcnt;
__device__ int   g_flaglist[B_ROWS];

// ============================================================
// PTX helpers
// ============================================================
__device__ __forceinline__ uint32_t smem_u32(const void* p) {
    uint32_t a;
    asm("{ .reg .u64 t; cvta.to.shared.u64 t, %1; cvt.u32.u64 %0, t; }"
        : "=r"(a) : "l"(p));
    return a;
}
__device__ __forceinline__ void cp16(uint32_t s, const void* g) {
    asm volatile("cp.async.cg.shared.global [%0], [%1], 16;" :: "r"(s), "l"(g));
}
#define CP_COMMIT() asm volatile("cp.async.commit_group;" ::: "memory")
#define CP_WAIT(n)  asm volatile("cp.async.wait_group %0;" :: "n"(n) : "memory")

__device__ __forceinline__ void ldsm4(uint32_t* r, uint32_t addr) {
    asm volatile("ldmatrix.sync.aligned.m8n8.x4.shared.b16 {%0,%1,%2,%3}, [%4];"
        : "=r"(r[0]), "=r"(r[1]), "=r"(r[2]), "=r"(r[3]) : "r"(addr));
}
__device__ __forceinline__ void mma16816(float* c, const uint32_t* a, const uint32_t* b) {
    asm volatile(
        "mma.sync.aligned.m16n8k16.row.col.f32.f16.f16.f32 "
        "{%0,%1,%2,%3}, {%4,%5,%6,%7}, {%8,%9}, {%0,%1,%2,%3};"
        : "+f"(c[0]), "+f"(c[1]), "+f"(c[2]), "+f"(c[3])
        : "r"(a[0]), "r"(a[1]), "r"(a[2]), "r"(a[3]), "r"(b[0]), "r"(b[1]));
}
__device__ __forceinline__ uint32_t sw_addr(uint32_t base, int row, int unit) {
    return base + (uint32_t)(row * 128) + (uint32_t)((unit ^ (row & 7)) << 4);
}

// top-2 tuple helpers (ties -> lower index)
struct Top2 { float v1; int i1; float v2; int i2; };
__device__ __forceinline__ void t2_insert(Top2& t, float v, int c) {
    if (v > t.v1 || (v == t.v1 && c < t.i1)) {
        t.v2 = t.v1; t.i2 = t.i1; t.v1 = v; t.i1 = c;
    } else if (v > t.v2 || (v == t.v2 && c < t.i2)) {
        t.v2 = v; t.i2 = c;
    }
}
__device__ __forceinline__ void t2_merge(Top2& a, const Top2& b) {
    if (b.v1 > a.v1 || (b.v1 == a.v1 && b.i1 < a.i1)) {
        if (a.v1 > b.v2 || (a.v1 == b.v2 && a.i1 < b.i2)) { a.v2 = a.v1; a.i2 = a.i1; }
        else { a.v2 = b.v2; a.i2 = b.i2; }
        a.v1 = b.v1; a.i1 = b.i1;
    } else {
        if (b.v1 > a.v2 || (b.v1 == a.v2 && b.i1 < a.i2)) { a.v2 = b.v1; a.i2 = b.i1; }
    }
}

// ============================================================
// GEMM (single fp16 plane) + fused per-tile top-2
// grid: (B_ROWS/256=32, K_CB/128=32), 256 threads
// 8 warps: warpM = wid>>1 (0..3), warpN = wid&1 (0..1); warp tile 64x64
// ============================================================
__device__ __forceinline__ void fill_stage(uint32_t st, int tileM, int tileN,
                                           int kc, int tid) {
    const __half* a0 = g_rh0 + ((size_t)tileM * BM) * D_DIM + kc * BK;
    const __half* b0 = g_cb0 + ((size_t)tileN * BN) * D_DIM + kc * BK;
    // A: 256 rows x 8 units = 2048 chunks of 16B; 256 thr -> 8 iters
    #pragma unroll
    for (int i = 0; i < 8; i++) {
        int c = tid + i * 256;
        int row = c >> 3, u = c & 7;
        uint32_t sw = (uint32_t)(row * 128) + (uint32_t)((u ^ (row & 7)) << 4);
        cp16(st + sw, a0 + (size_t)row * D_DIM + (u << 3));
    }
    // B: 128 rows x 8 units = 1024 chunks; 4 iters
    #pragma unroll
    for (int i = 0; i < 4; i++) {
        int c = tid + i * 256;
        int row = c >> 3, u = c & 7;
        uint32_t sw = (uint32_t)(row * 128) + (uint32_t)((u ^ (row & 7)) << 4);
        cp16(st + A_BYTES + sw, b0 + (size_t)row * D_DIM + (u << 3));
    }
}

__global__ void __launch_bounds__(256, 1) gemm_argmax_kernel() {
    extern __shared__ char smem[];
    uint32_t sb = smem_u32(smem);
    const int tid = threadIdx.x;
    const int tileM = blockIdx.x, tileN = blockIdx.y;
    const int wid = tid >> 5, lane = tid & 31;
    const int warpM = wid >> 1, warpN = wid & 1;
    const int grp = lane >> 2, qc = lane & 3;

    if (tileM == 0 && tileN == 0 && tid == 0) g_flagcnt = 0;

    float acc[4][8][4];
    #pragma unroll
    for (int mi = 0; mi < 4; mi++)
        #pragma unroll
        for (int ni = 0; ni < 8; ni++)
            #pragma unroll
            for (int j = 0; j < 4; j++) acc[mi][ni][j] = 0.f;

    // prologue: fill stages 0..2
    fill_stage(sb, tileM, tileN, 0, tid);                      CP_COMMIT();
    fill_stage(sb + STAGE_BYTES, tileM, tileN, 1, tid);        CP_COMMIT();
    fill_stage(sb + 2 * STAGE_BYTES, tileM, tileN, 2, tid);    CP_COMMIT();

    #pragma unroll 1
    for (int kc = 0; kc < NKCH; kc++) {
        if (kc < NKCH - 2)      { CP_WAIT(2); }
        else if (kc == NKCH - 2){ CP_WAIT(1); }
        else                    { CP_WAIT(0); }
        __syncthreads();

        if (kc + 3 < NKCH) {
            fill_stage(sb + (uint32_t)(((kc + 3) % NSTAGE) * STAGE_BYTES),
                       tileM, tileN, kc + 3, tid);
            CP_COMMIT();
        }

        uint32_t st = sb + (uint32_t)((kc % NSTAGE) * STAGE_BYTES);
        uint32_t aBase = st;
        uint32_t bBase = st + A_BYTES;
        const int aRowB = warpM * 64 + (lane & 15);
        const int bRowB = warpN * 64 + ((lane >> 4) << 3) + (lane & 7);

        #pragma unroll
        for (int ks = 0; ks < 4; ks++) {
            const int u = ks * 2;
            const int aU = u + (lane >> 4);
            const int bU = u + ((lane >> 3) & 1);

            uint32_t af[4][4], bf[8][2];
            #pragma unroll
            for (int mi = 0; mi < 4; mi++)
                ldsm4(af[mi], sw_addr(aBase, aRowB + mi * 16, aU));
            #pragma unroll
            for (int nb = 0; nb < 4; nb++) {
                uint32_t r[4];
                ldsm4(r, sw_addr(bBase, bRowB + nb * 16, bU));
                bf[nb * 2 + 0][0] = r[0]; bf[nb * 2 + 0][1] = r[1];
                bf[nb * 2 + 1][0] = r[2]; bf[nb * 2 + 1][1] = r[3];
            }
            #pragma unroll
            for (int mi = 0; mi < 4; mi++)
                #pragma unroll
                for (int ni = 0; ni < 8; ni++)
                    mma16816(acc[mi][ni], af[mi], bf[ni]);
        }
    }

    __syncthreads();  // compute done before smem reuse

    // ---------------- epilogue: per-tile top-2 ----------------
    float* sv1 = (float*)smem;                       // [256][2]
    int*   si1 = (int*)(smem + 2048);
    float* sv2 = (float*)(smem + 4096);
    int*   si2 = (int*)(smem + 6144);

    #pragma unroll
    for (int mi = 0; mi < 4; mi++) {
        Top2 lo = {-3.4e38f, 0x7fffffff, -3.4e38f, 0x7fffffff};
        Top2 hi = {-3.4e38f, 0x7fffffff, -3.4e38f, 0x7fffffff};
        #pragma unroll
        for (int ni = 0; ni < 8; ni++) {
            #pragma unroll
            for (int j = 0; j < 2; j++) {
                int c = warpN * 64 + ni * 8 + qc * 2 + j;
                t2_insert(lo, acc[mi][ni][j], c);
                t2_insert(hi, acc[mi][ni][2 + j], c);
            }
        }
        #pragma unroll
        for (int off = 1; off < 4; off <<= 1) {
            Top2 o;
            o.v1 = __shfl_xor_sync(0xffffffffu, lo.v1, off);
            o.i1 = __shfl_xor_sync(0xffffffffu, lo.i1, off);
            o.v2 = __shfl_xor_sync(0xffffffffu, lo.v2, off);
            o.i2 = __shfl_xor_sync(0xffffffffu, lo.i2, off);
            t2_merge(lo, o);
            o.v1 = __shfl_xor_sync(0xffffffffu, hi.v1, off);
            o.i1 = __shfl_xor_sync(0xffffffffu, hi.i1, off);
            o.v2 = __shfl_xor_sync(0xffffffffu, hi.v2, off);
            o.i2 = __shfl_xor_sync(0xffffffffu, hi.i2, off);
            t2_merge(hi, o);
        }
        if (qc == 0) {
            int rLo = warpM * 64 + mi * 16 + grp;
            sv1[rLo * 2 + warpN] = lo.v1;  si1[rLo * 2 + warpN] = lo.i1;
            sv2[rLo * 2 + warpN] = lo.v2;  si2[rLo * 2 + warpN] = lo.i2;
            int rHi = rLo + 8;
            sv1[rHi * 2 + warpN] = hi.v1;  si1[rHi * 2 + warpN] = hi.i1;
            sv2[rHi * 2 + warpN] = hi.v2;  si2[rHi * 2 + warpN] = hi.i2;
        }
    }
    __syncthreads();

    {
        Top2 t = {sv1[tid * 2], si1[tid * 2], sv2[tid * 2], si2[tid * 2]};
        Top2 o = {sv1[tid * 2 + 1], si1[tid * 2 + 1],
                  sv2[tid * 2 + 1], si2[tid * 2 + 1]};
        t2_merge(t, o);
        size_t oo = (size_t)(tileM * BM + tid) * NT + tileN;
        g_t1v[oo] = t.v1;  g_t1i[oo] = tileN * BN + t.i1;
        g_t2v[oo] = t.v2;  g_t2i[oo] = tileN * BN + t.i2;
    }
}

// ============================================================
// select: per-row top-2 merge over 32 tiles, flag near-ties
// ============================================================
__global__ void select_kernel() {
    int tid = threadIdx.x, lane = tid & 31, wid = tid >> 5;
    int r = blockIdx.x * 8 + wid;
    size_t o = (size_t)r * NT + lane;
    float v1 = g_t1v[o];
    int   i1 = g_t1i[o];
    float v2 = g_t2v[o];
    #pragma unroll
    for (int off = 16; off > 0; off >>= 1) {
        float ov1 = __shfl_xor_sync(0xffffffffu, v1, off);
        int   oi1 = __shfl_xor_sync(0xffffffffu, i1, off);
        float ov2 = __shfl_xor_sync(0xffffffffu, v2, off);
        if (ov1 > v1 || (ov1 == v1 && oi1 < i1)) {
            v2 = fmaxf(ov2, v1);
            v1 = ov1; i1 = oi1;
        } else {
            v2 = fmaxf(v2, ov1);
        }
    }
    if (lane == 0) {
        g_choice[r] = i1;
        if (v1 - v2 < THR) {
            int p = atomicAdd(&g_flagcnt, 1);
            g_flaglist[p] = r;
        }
    }
}

// ============================================================
// refine: flagged rows -> Kahan fp32 dots on 64 candidates
// ============================================================
__global__ void refine_kernel(const float* __restrict__ cb) {
    __shared__ float sres[D_DIM];
    __shared__ float sv[64];
    __shared__ int   si[64];
    int tid = threadIdx.x, lane = tid & 31, wid = tid >> 5;
    int cnt = *(volatile int*)&g_flagcnt;

    for (int f = blockIdx.x; f < cnt; f += gridDim.x) {
        int r = g_flaglist[f];
        const float4* r4 = (const float4*)(g_resid + (size_t)r * D_DIM);
        ((float4*)sres)[tid] = r4[tid];
        __syncthreads();

        for (int c = wid; c < 64; c += 8) {
            int tile = c >> 1;
            size_t to = (size_t)r * NT + tile;
            int idx = (c & 1) ? g_t2i[to] : g_t1i[to];
            const float* cbr = cb + (size_t)idx * D_DIM;
            float s = 0.f, comp = 0.f;
            for (int e = lane; e < D_DIM; e += 32) {
                float prod = sres[e] * cbr[e];
                float y = prod - comp;
                float t = s + y;
                comp = (t - s) - y;
                s = t;
            }
            #pragma unroll
            for (int off = 16; off > 0; off >>= 1)
                s += __shfl_xor_sync(0xffffffffu, s, off);
            if (lane == 0) { sv[c] = s; si[c] = idx; }
        }
        __syncthreads();
        if (tid == 0) {
            float bv = -3.4e38f; int bi = 0x7fffffff;
            #pragma unroll
            for (int c = 0; c < 64; c++) {
                float v = sv[c]; int i = si[c];
                if (v > bv || (v == bv && i < bi)) { bv = v; bi = i; }
            }
            g_choice[r] = bi;
        }
        __syncthreads();
    }
}

// ============================================================
// init / split
// ============================================================
__global__ void split_cb_kernel(const float* __restrict__ cb) {
    int r = blockIdx.x;
    const float4* c4 = (const float4*)(cb + (size_t)r * D_DIM);
    __half2* h0p = (__half2*)(g_cb0 + (size_t)r * D_DIM);
    int tid = threadIdx.x;
    float4 v = c4[tid];
    h0p[tid * 2 + 0] = __float22half2_rn(make_float2(v.x, v.y));
    h0p[tid * 2 + 1] = __float22half2_rn(make_float2(v.z, v.w));
}

__global__ void init_kernel(const float* __restrict__ targets) {
    int r = blockIdx.x;
    int tid = threadIdx.x;
    int lane = tid & 31, wid = tid >> 5;
    __shared__ float wsum[8];

    const float4* t4 = (const float4*)(targets + (size_t)r * D_DIM);
    float4* r4 = (float4*)(g_resid + (size_t)r * D_DIM);
    __half2* h0p = (__half2*)(g_rh0 + (size_t)r * D_DIM);

    float4 v = t4[tid];
    r4[tid] = v;
    h0p[tid * 2 + 0] = __float22half2_rn(make_float2(v.x, v.y));
    h0p[tid * 2 + 1] = __float22half2_rn(make_float2(v.z, v.w));

    float local = v.x * v.x + v.y * v.y + v.z * v.z + v.w * v.w;
    #pragma unroll
    for (int off = 16; off > 0; off >>= 1)
        local += __shfl_xor_sync(0xffffffffu, local, off);
    if (lane == 0) wsum[wid] = local;
    __syncthreads();
    if (tid == 0) {
        float s = 0.f;
        #pragma unroll
        for (int w = 0; w < 8; w++) s += wsum[w];
        g_norm2[r] = s;
        g_active[r] = 1;
    }
}

// ============================================================
// update residual
// ============================================================
__global__ void update_kernel(const float* __restrict__ cb, int step, float decay) {
    int r = blockIdx.x;
    int tid = threadIdx.x;
    int lane = tid & 31, wid = tid >> 5;
    __shared__ int s_idx, s_act;
    __shared__ float wsum[8];

    if (tid == 0) {
        int i = g_choice[r];
        int act = g_active[r] && (sqrtf(g_norm2[r]) >= RES_TH);
        g_active[r] = act;
        g_indices[(size_t)r * L_STEPS + step] = act ? i : -1;
        s_idx = i;
        s_act = act;
    }
    __syncthreads();
    if (!s_act) return;

    int idx = s_idx;
    float4* r4 = (float4*)(g_resid + (size_t)r * D_DIM);
    const float4* c4 = (const float4*)(cb + (size_t)idx * D_DIM);
    __half2* h0p = (__half2*)(g_rh0 + (size_t)r * D_DIM);

    float4 v = r4[tid];
    float4 c = c4[tid];
    v.x = __fsub_rn(v.x, __fmul_rn(decay, c.x));
    v.y = __fsub_rn(v.y, __fmul_rn(decay, c.y));
    v.z = __fsub_rn(v.z, __fmul_rn(decay, c.z));
    v.w = __fsub_rn(v.w, __fmul_rn(decay, c.w));
    r4[tid] = v;
    h0p[tid * 2 + 0] = __float22half2_rn(make_float2(v.x, v.y));
    h0p[tid * 2 + 1] = __float22half2_rn(make_float2(v.z, v.w));

    float local = v.x * v.x + v.y * v.y + v.z * v.z + v.w * v.w;
    #pragma unroll
    for (int off = 16; off > 0; off >>= 1)
        local += __shfl_xor_sync(0xffffffffu, local, off);
    if (lane == 0) wsum[wid] = local;
    __syncthreads();
    if (tid == 0) {
        float s = 0.f;
        #pragma unroll
        for (int w = 0; w < 8; w++) s += wsum[w];
        g_norm2[r] = s;
    }
}

// ============================================================
// finalize variants
// ============================================================
__global__ void out_both_f32(float* __restrict__ out) {
    int r = blockIdx.x;
    for (int c = threadIdx.x; c < D_DIM; c += 256)
        out[(size_t)B_ROWS * L_STEPS + (size_t)r * D_DIM + c] = g_resid[(size_t)r * D_DIM + c];
    if (threadIdx.x < L_STEPS)
        out[(size_t)r * L_STEPS + threadIdx.x] = (float)g_indices[(size_t)r * L_STEPS + threadIdx.x];
}
__global__ void out_idx_i32(int* __restrict__ out) {
    int i = blockIdx.x * 256 + threadIdx.x;
    if (i < B_ROWS * L_STEPS) out[i] = g_indices[i];
}
__global__ void out_res_f32(float* __restrict__ out) {
    int r = blockIdx.x;
    for (int c = threadIdx.x; c < D_DIM; c += 256)
        out[(size_t)r * D_DIM + c] = g_resid[(size_t)r * D_DIM + c];
}

// ============================================================
// host launcher
// ============================================================
extern "C" void kernel_launch(void* const* d_in, const int* in_sizes, int n_in,
                              void* d_out, int out_size) {
    const float* targets  = (const float*)d_in[0];
    const float* codebook = (const float*)d_in[1];

    cudaFuncSetAttribute(gemm_argmax_kernel,
                         cudaFuncAttributeMaxDynamicSharedMemorySize, SMEM_TOTAL);

    split_cb_kernel<<<K_CB, 256>>>(codebook);
    init_kernel<<<B_ROWS, 256>>>(targets);

    for (int s = 0; s < L_STEPS; s++) {
        dim3 grid(B_ROWS / BM, K_CB / BN);
        gemm_argmax_kernel<<<grid, 256, SMEM_TOTAL>>>();
        select_kernel<<<B_ROWS / 8, 256>>>();
        refine_kernel<<<128, 256>>>(codebook);
        float decay = (float)pow(0.9, (double)s);
        update_kernel<<<B_ROWS, 256>>>(codebook, s, decay);
    }

    if (out_size == B_ROWS * L_STEPS) {
        out_idx_i32<<<(B_ROWS * L_STEPS + 255) / 256, 256>>>((int*)d_out);
    } else if (out_size == B_ROWS * D_DIM) {
        out_res_f32<<<B_ROWS, 256>>>((float*)d_out);
    } else {
        out_both_f32<<<B_ROWS, 256>>>((float*)d_out);
    }
}

// round 7
// speedup vs baseline: 3.3947x; 2.1992x over previous
#include <cuda_runtime.h>
#include <cuda_fp16.h>
#include <cstdint>
#include <math.h>

// ============================================================
// Problem constants
// ============================================================
#define B_ROWS 8192
#define D_DIM  1024
#define K_CB   4096
#define L_STEPS 8
#define RES_TH 1e-3f
#define THR    0.30f

// scores GEMM tiling: CTA 256x128, warp tile 64x64
#define BM 256
#define BN 128
#define BK 64
#define NT    (K_CB / BN)     // 32
#define NKCH  (D_DIM / BK)    // 16
#define NSTAGE 4
#define A_BYTES (BM * BK * 2)
#define B_BYTES (BN * BK * 2)
#define STAGE_BYTES (A_BYTES + B_BYTES)        // 49152
#define SMEM_TOTAL  (NSTAGE * STAGE_BYTES)     // 196608

// gram GEMM tiling: CTA 128x128, 3 fp16-split passes, 3 stages
#define GPLANE (128 * BK * 2)                  // 16384
#define GSTAGE (4 * GPLANE)                    // 65536
#define GSMEM  (3 * GSTAGE)                    // 196608

// ============================================================
// Device scratch — every array <= 32 MB (eager module-load commit)
// ============================================================
__device__ __align__(128) float  g_resid[B_ROWS * D_DIM];            // 32 MB
__device__ __align__(128) __half g_rh0[B_ROWS * D_DIM];              // 16 MB
__device__ __align__(128) __half g_cb0[K_CB * D_DIM];                // 8 MB
__device__ __align__(128) __half g_cb1[K_CB * D_DIM];                // 8 MB
// scores fp32: 8192 x 4096 = 128 MB in 4 chunks of 2048 rows (32 MB)
#define SC_CHUNK_ROWS 2048
__device__ __align__(128) float g_sc0[SC_CHUNK_ROWS * K_CB];
__device__ __align__(128) float g_sc1[SC_CHUNK_ROWS * K_CB];
__device__ __align__(128) float g_sc2[SC_CHUNK_ROWS * K_CB];
__device__ __align__(128) float g_sc3[SC_CHUNK_ROWS * K_CB];
// Gram fp32: 4096 x 4096 = 64 MB in 2 chunks of 2048 rows (32 MB)
__device__ __align__(128) float g_G0[SC_CHUNK_ROWS * K_CB];
__device__ __align__(128) float g_G1[SC_CHUNK_ROWS * K_CB];

__device__ float g_t1v[B_ROWS * NT];
__device__ int   g_t1i[B_ROWS * NT];
__device__ float g_t2v[B_ROWS * NT];
__device__ int   g_t2i[B_ROWS * NT];
__device__ float g_rowt1v[B_ROWS];
__device__ int   g_rowt1i[B_ROWS];
__device__ float g_rowt2v[B_ROWS];
__device__ float g_norm2[B_ROWS];
__device__ int   g_active[B_ROWS];
__device__ int   g_indices[B_ROWS * L_STEPS];
__device__ int   g_choice[B_ROWS];
__device__ int   g_flagcnt;
__device__ int   g_flaglist[B_ROWS];

__device__ __forceinline__ float* score_row(int r) {
    int c = r >> 11;
    float* b = (c == 0) ? g_sc0 : (c == 1) ? g_sc1 : (c == 2) ? g_sc2 : g_sc3;
    return b + (size_t)(r & (SC_CHUNK_ROWS - 1)) * K_CB;
}
__device__ __forceinline__ float* G_row(int k) {
    float* b = (k >> 11) ? g_G1 : g_G0;
    return b + (size_t)(k & (SC_CHUNK_ROWS - 1)) * K_CB;
}

// ============================================================
// PTX helpers
// ============================================================
__device__ __forceinline__ uint32_t smem_u32(const void* p) {
    uint32_t a;
    asm("{ .reg .u64 t; cvta.to.shared.u64 t, %1; cvt.u32.u64 %0, t; }"
        : "=r"(a) : "l"(p));
    return a;
}
__device__ __forceinline__ void cp16(uint32_t s, const void* g) {
    asm volatile("cp.async.cg.shared.global [%0], [%1], 16;" :: "r"(s), "l"(g));
}
#define CP_COMMIT() asm volatile("cp.async.commit_group;" ::: "memory")
#define CP_WAIT(n)  asm volatile("cp.async.wait_group %0;" :: "n"(n) : "memory")

__device__ __forceinline__ void ldsm4(uint32_t* r, uint32_t addr) {
    asm volatile("ldmatrix.sync.aligned.m8n8.x4.shared.b16 {%0,%1,%2,%3}, [%4];"
        : "=r"(r[0]), "=r"(r[1]), "=r"(r[2]), "=r"(r[3]) : "r"(addr));
}
__device__ __forceinline__ void mma16816(float* c, const uint32_t* a, const uint32_t* b) {
    asm volatile(
        "mma.sync.aligned.m16n8k16.row.col.f32.f16.f16.f32 "
        "{%0,%1,%2,%3}, {%4,%5,%6,%7}, {%8,%9}, {%0,%1,%2,%3};"
        : "+f"(c[0]), "+f"(c[1]), "+f"(c[2]), "+f"(c[3])
        : "r"(a[0]), "r"(a[1]), "r"(a[2]), "r"(a[3]), "r"(b[0]), "r"(b[1]));
}
__device__ __forceinline__ uint32_t sw_addr(uint32_t base, int row, int unit) {
    return base + (uint32_t)(row * 128) + (uint32_t)((unit ^ (row & 7)) << 4);
}

struct Top2 { float v1; int i1; float v2; int i2; };
__device__ __forceinline__ void t2_insert(Top2& t, float v, int c) {
    if (v > t.v1 || (v == t.v1 && c < t.i1)) {
        t.v2 = t.v1; t.i2 = t.i1; t.v1 = v; t.i1 = c;
    } else if (v > t.v2 || (v == t.v2 && c < t.i2)) {
        t.v2 = v; t.i2 = c;
    }
}
__device__ __forceinline__ void t2_merge(Top2& a, const Top2& b) {
    if (b.v1 > a.v1 || (b.v1 == a.v1 && b.i1 < a.i1)) {
        if (a.v1 > b.v2 || (a.v1 == b.v2 && a.i1 < b.i2)) { a.v2 = a.v1; a.i2 = a.i1; }
        else { a.v2 = b.v2; a.i2 = b.i2; }
        a.v1 = b.v1; a.i1 = b.i1;
    } else {
        if (b.v1 > a.v2 || (b.v1 == a.v2 && b.i1 < a.i2)) { a.v2 = b.v1; a.i2 = b.i1; }
    }
}

// ============================================================
// Gram kernel: G = cb @ cb^T, 3-pass fp16-split, fp32 out
// grid (32, 32), 256 thr, 8 warps (2M x 4N), warp tile 64x32
// ============================================================
__device__ __forceinline__ void fill_gram(uint32_t st, int tileM, int tileN,
                                          int kc, int tid) {
    const __half* a0 = g_cb0 + ((size_t)tileM * 128) * D_DIM + kc * BK;
    const __half* a1 = g_cb1 + ((size_t)tileM * 128) * D_DIM + kc * BK;
    const __half* b0 = g_cb0 + ((size_t)tileN * 128) * D_DIM + kc * BK;
    const __half* b1 = g_cb1 + ((size_t)tileN * 128) * D_DIM + kc * BK;
    #pragma unroll
    for (int i = 0; i < 4; i++) {
        int c = tid + i * 256;
        int row = c >> 3, u = c & 7;
        uint32_t sw = (uint32_t)(row * 128) + (uint32_t)((u ^ (row & 7)) << 4);
        size_t go = (size_t)row * D_DIM + (u << 3);
        cp16(st + 0 * GPLANE + sw, a0 + go);
        cp16(st + 1 * GPLANE + sw, a1 + go);
        cp16(st + 2 * GPLANE + sw, b0 + go);
        cp16(st + 3 * GPLANE + sw, b1 + go);
    }
}

__global__ void __launch_bounds__(256, 1) gram_kernel() {
    extern __shared__ char smem[];
    uint32_t sb = smem_u32(smem);
    const int tid = threadIdx.x;
    const int tileM = blockIdx.x, tileN = blockIdx.y;
    const int wid = tid >> 5, lane = tid & 31;
    const int warpM = wid >> 2, warpN = wid & 3;
    const int grp = lane >> 2, qc = lane & 3;

    float acc[4][4][4];
    #pragma unroll
    for (int mi = 0; mi < 4; mi++)
        #pragma unroll
        for (int ni = 0; ni < 4; ni++)
            #pragma unroll
            for (int j = 0; j < 4; j++) acc[mi][ni][j] = 0.f;

    fill_gram(sb, tileM, tileN, 0, tid);           CP_COMMIT();
    fill_gram(sb + GSTAGE, tileM, tileN, 1, tid);  CP_COMMIT();

    #pragma unroll 1
    for (int kc = 0; kc < NKCH; kc++) {
        if (kc + 1 < NKCH) { CP_WAIT(1); } else { CP_WAIT(0); }
        __syncthreads();
        if (kc + 2 < NKCH) {
            fill_gram(sb + (uint32_t)(((kc + 2) % 3) * GSTAGE), tileM, tileN, kc + 2, tid);
            CP_COMMIT();
        }
        uint32_t st = sb + (uint32_t)((kc % 3) * GSTAGE);
        uint32_t aB0 = st, aB1 = st + GPLANE, bB0 = st + 2 * GPLANE, bB1 = st + 3 * GPLANE;
        const int aRowB = warpM * 64 + (lane & 15);
        const int bRowB = warpN * 32 + ((lane >> 4) << 3) + (lane & 7);
        #pragma unroll
        for (int ks = 0; ks < 4; ks++) {
            const int u = ks * 2;
            const int aU = u + (lane >> 4);
            const int bU = u + ((lane >> 3) & 1);
            uint32_t a0f[4][4], a1f[4][4], b0f[4][2], b1f[4][2];
            #pragma unroll
            for (int mi = 0; mi < 4; mi++)
                ldsm4(a0f[mi], sw_addr(aB0, aRowB + mi * 16, aU));
            #pragma unroll
            for (int nb = 0; nb < 2; nb++) {
                uint32_t r[4];
                ldsm4(r, sw_addr(bB0, bRowB + nb * 16, bU));
                b0f[nb * 2 + 0][0] = r[0]; b0f[nb * 2 + 0][1] = r[1];
                b0f[nb * 2 + 1][0] = r[2]; b0f[nb * 2 + 1][1] = r[3];
            }
            #pragma unroll
            for (int mi = 0; mi < 4; mi++)
                #pragma unroll
                for (int ni = 0; ni < 4; ni++)
                    mma16816(acc[mi][ni], a0f[mi], b0f[ni]);
            #pragma unroll
            for (int nb = 0; nb < 2; nb++) {
                uint32_t r[4];
                ldsm4(r, sw_addr(bB1, bRowB + nb * 16, bU));
                b1f[nb * 2 + 0][0] = r[0]; b1f[nb * 2 + 0][1] = r[1];
                b1f[nb * 2 + 1][0] = r[2]; b1f[nb * 2 + 1][1] = r[3];
            }
            #pragma unroll
            for (int mi = 0; mi < 4; mi++)
                #pragma unroll
                for (int ni = 0; ni < 4; ni++)
                    mma16816(acc[mi][ni], a0f[mi], b1f[ni]);
            #pragma unroll
            for (int mi = 0; mi < 4; mi++)
                ldsm4(a1f[mi], sw_addr(aB1, aRowB + mi * 16, aU));
            #pragma unroll
            for (int mi = 0; mi < 4; mi++)
                #pragma unroll
                for (int ni = 0; ni < 4; ni++)
                    mma16816(acc[mi][ni], a1f[mi], b0f[ni]);
        }
    }

    float* Gb = G_row(tileM * 128);
    #pragma unroll
    for (int mi = 0; mi < 4; mi++) {
        #pragma unroll
        for (int ni = 0; ni < 4; ni++) {
            int lr = warpM * 64 + mi * 16 + grp;
            int c0 = tileN * 128 + warpN * 32 + ni * 8 + qc * 2;
            *(float2*)&Gb[(size_t)lr * K_CB + c0] =
                make_float2(acc[mi][ni][0], acc[mi][ni][1]);
            *(float2*)&Gb[(size_t)(lr + 8) * K_CB + c0] =
                make_float2(acc[mi][ni][2], acc[mi][ni][3]);
        }
    }
}

// ============================================================
// scores GEMM (1-plane) + per-tile top-2
// ============================================================
__device__ __forceinline__ void fill_stage(uint32_t st, int tileM, int tileN,
                                           int kc, int tid) {
    const __half* a0 = g_rh0 + ((size_t)tileM * BM) * D_DIM + kc * BK;
    const __half* b0 = g_cb0 + ((size_t)tileN * BN) * D_DIM + kc * BK;
    #pragma unroll
    for (int i = 0; i < 8; i++) {
        int c = tid + i * 256;
        int row = c >> 3, u = c & 7;
        uint32_t sw = (uint32_t)(row * 128) + (uint32_t)((u ^ (row & 7)) << 4);
        cp16(st + sw, a0 + (size_t)row * D_DIM + (u << 3));
    }
    #pragma unroll
    for (int i = 0; i < 4; i++) {
        int c = tid + i * 256;
        int row = c >> 3, u = c & 7;
        uint32_t sw = (uint32_t)(row * 128) + (uint32_t)((u ^ (row & 7)) << 4);
        cp16(st + A_BYTES + sw, b0 + (size_t)row * D_DIM + (u << 3));
    }
}

__global__ void __launch_bounds__(256, 1) gemm0_kernel() {
    extern __shared__ char smem[];
    uint32_t sb = smem_u32(smem);
    const int tid = threadIdx.x;
    const int tileM = blockIdx.x, tileN = blockIdx.y;
    const int wid = tid >> 5, lane = tid & 31;
    const int warpM = wid >> 1, warpN = wid & 1;
    const int grp = lane >> 2, qc = lane & 3;

    if (tileM == 0 && tileN == 0 && tid == 0) g_flagcnt = 0;

    float acc[4][8][4];
    #pragma unroll
    for (int mi = 0; mi < 4; mi++)
        #pragma unroll
        for (int ni = 0; ni < 8; ni++)
            #pragma unroll
            for (int j = 0; j < 4; j++) acc[mi][ni][j] = 0.f;

    fill_stage(sb, tileM, tileN, 0, tid);                      CP_COMMIT();
    fill_stage(sb + STAGE_BYTES, tileM, tileN, 1, tid);        CP_COMMIT();
    fill_stage(sb + 2 * STAGE_BYTES, tileM, tileN, 2, tid);    CP_COMMIT();

    #pragma unroll 1
    for (int kc = 0; kc < NKCH; kc++) {
        if (kc < NKCH - 2)      { CP_WAIT(2); }
        else if (kc == NKCH - 2){ CP_WAIT(1); }
        else                    { CP_WAIT(0); }
        __syncthreads();
        if (kc + 3 < NKCH) {
            fill_stage(sb + (uint32_t)(((kc + 3) % NSTAGE) * STAGE_BYTES),
                       tileM, tileN, kc + 3, tid);
            CP_COMMIT();
        }
        uint32_t st = sb + (uint32_t)((kc % NSTAGE) * STAGE_BYTES);
        uint32_t aBase = st, bBase = st + A_BYTES;
        const int aRowB = warpM * 64 + (lane & 15);
        const int bRowB = warpN * 64 + ((lane >> 4) << 3) + (lane & 7);
        #pragma unroll
        for (int ks = 0; ks < 4; ks++) {
            const int u = ks * 2;
            const int aU = u + (lane >> 4);
            const int bU = u + ((lane >> 3) & 1);
            uint32_t af[4][4], bf[8][2];
            #pragma unroll
            for (int mi = 0; mi < 4; mi++)
                ldsm4(af[mi], sw_addr(aBase, aRowB + mi * 16, aU));
            #pragma unroll
            for (int nb = 0; nb < 4; nb++) {
                uint32_t r[4];
                ldsm4(r, sw_addr(bBase, bRowB + nb * 16, bU));
                bf[nb * 2 + 0][0] = r[0]; bf[nb * 2 + 0][1] = r[1];
                bf[nb * 2 + 1][0] = r[2]; bf[nb * 2 + 1][1] = r[3];
            }
            #pragma unroll
            for (int mi = 0; mi < 4; mi++)
                #pragma unroll
                for (int ni = 0; ni < 8; ni++)
                    mma16816(acc[mi][ni], af[mi], bf[ni]);
        }
    }

    // store scores
    {
        float* scb = score_row(tileM * BM);
        #pragma unroll
        for (int mi = 0; mi < 4; mi++) {
            #pragma unroll
            for (int ni = 0; ni < 8; ni++) {
                int lr = warpM * 64 + mi * 16 + grp;
                int c0 = tileN * BN + warpN * 64 + ni * 8 + qc * 2;
                *(float2*)&scb[(size_t)lr * K_CB + c0] =
                    make_float2(acc[mi][ni][0], acc[mi][ni][1]);
                *(float2*)&scb[(size_t)(lr + 8) * K_CB + c0] =
                    make_float2(acc[mi][ni][2], acc[mi][ni][3]);
            }
        }
    }

    __syncthreads();
    float* sv1 = (float*)smem;
    int*   si1 = (int*)(smem + 2048);
    float* sv2 = (float*)(smem + 4096);
    int*   si2 = (int*)(smem + 6144);

    #pragma unroll
    for (int mi = 0; mi < 4; mi++) {
        Top2 lo = {-3.4e38f, 0x7fffffff, -3.4e38f, 0x7fffffff};
        Top2 hi = {-3.4e38f, 0x7fffffff, -3.4e38f, 0x7fffffff};
        #pragma unroll
        for (int ni = 0; ni < 8; ni++) {
            #pragma unroll
            for (int j = 0; j < 2; j++) {
                int c = warpN * 64 + ni * 8 + qc * 2 + j;
                t2_insert(lo, acc[mi][ni][j], c);
                t2_insert(hi, acc[mi][ni][2 + j], c);
            }
        }
        #pragma unroll
        for (int off = 1; off < 4; off <<= 1) {
            Top2 o;
            o.v1 = __shfl_xor_sync(0xffffffffu, lo.v1, off);
            o.i1 = __shfl_xor_sync(0xffffffffu, lo.i1, off);
            o.v2 = __shfl_xor_sync(0xffffffffu, lo.v2, off);
            o.i2 = __shfl_xor_sync(0xffffffffu, lo.i2, off);
            t2_merge(lo, o);
            o.v1 = __shfl_xor_sync(0xffffffffu, hi.v1, off);
            o.i1 = __shfl_xor_sync(0xffffffffu, hi.i1, off);
            o.v2 = __shfl_xor_sync(0xffffffffu, hi.v2, off);
            o.i2 = __shfl_xor_sync(0xffffffffu, hi.i2, off);
            t2_merge(hi, o);
        }
        if (qc == 0) {
            int rLo = warpM * 64 + mi * 16 + grp;
            sv1[rLo * 2 + warpN] = lo.v1;  si1[rLo * 2 + warpN] = lo.i1;
            sv2[rLo * 2 + warpN] = lo.v2;  si2[rLo * 2 + warpN] = lo.i2;
            int rHi = rLo + 8;
            sv1[rHi * 2 + warpN] = hi.v1;  si1[rHi * 2 + warpN] = hi.i1;
            sv2[rHi * 2 + warpN] = hi.v2;  si2[rHi * 2 + warpN] = hi.i2;
        }
    }
    __syncthreads();
    {
        Top2 t = {sv1[tid * 2], si1[tid * 2], sv2[tid * 2], si2[tid * 2]};
        Top2 o = {sv1[tid * 2 + 1], si1[tid * 2 + 1],
                  sv2[tid * 2 + 1], si2[tid * 2 + 1]};
        t2_merge(t, o);
        size_t oo = (size_t)(tileM * BM + tid) * NT + tileN;
        g_t1v[oo] = t.v1;  g_t1i[oo] = tileN * BN + t.i1;
        g_t2v[oo] = t.v2;  g_t2i[oo] = tileN * BN + t.i2;
    }
}

// ============================================================
// select step 0 / steps >= 1
// ============================================================
__global__ void select_tiles_kernel() {
    int tid = threadIdx.x, lane = tid & 31, wid = tid >> 5;
    int r = blockIdx.x * 8 + wid;
    size_t o = (size_t)r * NT + lane;
    float v1 = g_t1v[o];
    int   i1 = g_t1i[o];
    float v2 = g_t2v[o];
    #pragma unroll
    for (int off = 16; off > 0; off >>= 1) {
        float ov1 = __shfl_xor_sync(0xffffffffu, v1, off);
        int   oi1 = __shfl_xor_sync(0xffffffffu, i1, off);
        float ov2 = __shfl_xor_sync(0xffffffffu, v2, off);
        if (ov1 > v1 || (ov1 == v1 && oi1 < i1)) {
            v2 = fmaxf(ov2, v1);
            v1 = ov1; i1 = oi1;
        } else {
            v2 = fmaxf(v2, ov1);
        }
    }
    if (lane == 0) {
        g_choice[r] = i1;
        g_rowt1v[r] = v1;
        if (v1 - v2 < THR) {
            int p = atomicAdd(&g_flagcnt, 1);
            g_flaglist[p] = r;
        }
    }
}

__global__ void select_rows_kernel() {
    int r = blockIdx.x * 256 + threadIdx.x;
    if (r >= B_ROWS) return;
    g_choice[r] = g_rowt1i[r];
    if (g_rowt1v[r] - g_rowt2v[r] < THR) {
        int p = atomicAdd(&g_flagcnt, 1);
        g_flaglist[p] = r;
    }
}

// ============================================================
// refine: flagged rows, exact Kahan dots on candidates
// ============================================================
__global__ void refine_kernel(const float* __restrict__ cb) {
    __shared__ float sres[D_DIM];
    __shared__ int scand[128];
    __shared__ int scnt;
    __shared__ float sbv[8];
    __shared__ int   sbi[8];
    int tid = threadIdx.x, lane = tid & 31, wid = tid >> 5;
    int cnt = *(volatile int*)&g_flagcnt;

    for (int f = blockIdx.x; f < cnt; f += gridDim.x) {
        int r = g_flaglist[f];
        ((float4*)sres)[tid] = ((const float4*)(g_resid + (size_t)r * D_DIM))[tid];
        if (tid == 0) scnt = 0;
        __syncthreads();

        float thr = g_rowt1v[r] - THR;
        const float4* sc = (const float4*)score_row(r);
        #pragma unroll
        for (int i = 0; i < 4; i++) {
            int e = i * 256 + tid;
            float4 v = sc[e];
            int k = e * 4;
            if (v.x > thr) { int p = atomicAdd(&scnt, 1); if (p < 128) scand[p] = k; }
            if (v.y > thr) { int p = atomicAdd(&scnt, 1); if (p < 128) scand[p] = k + 1; }
            if (v.z > thr) { int p = atomicAdd(&scnt, 1); if (p < 128) scand[p] = k + 2; }
            if (v.w > thr) { int p = atomicAdd(&scnt, 1); if (p < 128) scand[p] = k + 3; }
        }
        __syncthreads();
        int nc = min(scnt, 128);

        float bv = -3.4e38f; int bi = 0x7fffffff;
        for (int c = wid; c < nc; c += 8) {
            int k = scand[c];
            const float* cbr = cb + (size_t)k * D_DIM;
            float s = 0.f, comp = 0.f;
            for (int e = lane; e < D_DIM; e += 32) {
                float prod = sres[e] * cbr[e];
                float y = prod - comp;
                float t = s + y;
                comp = (t - s) - y;
                s = t;
            }
            #pragma unroll
            for (int off = 16; off > 0; off >>= 1)
                s += __shfl_xor_sync(0xffffffffu, s, off);
            if (s > bv || (s == bv && k < bi)) { bv = s; bi = k; }
        }
        if (lane == 0) { sbv[wid] = bv; sbi[wid] = bi; }
        __syncthreads();
        if (tid == 0) {
            float v = sbv[0]; int i = sbi[0];
            #pragma unroll
            for (int w = 1; w < 8; w++)
                if (sbv[w] > v || (sbv[w] == v && sbi[w] < i)) { v = sbv[w]; i = sbi[w]; }
            g_choice[r] = i;
        }
        __syncthreads();
    }
}

// ============================================================
// scores incremental update + per-row top-2 for next step
// ============================================================
__global__ void scores_update_kernel(float decay) {
    int r = blockIdx.x;
    int tid = threadIdx.x, lane = tid & 31, wid = tid >> 5;
    __shared__ float wv1[8]; __shared__ int wi1[8]; __shared__ float wv2[8];

    if (r == 0 && tid == 0) g_flagcnt = 0;
    if (!g_active[r]) return;

    int cidx = g_choice[r];
    const float4* G4 = (const float4*)G_row(cidx);
    float4* sc = (float4*)score_row(r);

    float v1 = -3.4e38f; int i1 = 0x7fffffff; float v2 = -3.4e38f;
    #pragma unroll
    for (int i = 0; i < 4; i++) {
        int e = i * 256 + tid;
        float4 v = sc[e];
        float4 g = G4[e];
        v.x -= decay * g.x;
        v.y -= decay * g.y;
        v.z -= decay * g.z;
        v.w -= decay * g.w;
        sc[e] = v;
        int k = e * 4;
        if (v.x > v1 || (v.x == v1 && k < i1)) { v2 = v1; v1 = v.x; i1 = k; }
        else v2 = fmaxf(v2, v.x);
        if (v.y > v1 || (v.y == v1 && k + 1 < i1)) { v2 = v1; v1 = v.y; i1 = k + 1; }
        else v2 = fmaxf(v2, v.y);
        if (v.z > v1 || (v.z == v1 && k + 2 < i1)) { v2 = v1; v1 = v.z; i1 = k + 2; }
        else v2 = fmaxf(v2, v.z);
        if (v.w > v1 || (v.w == v1 && k + 3 < i1)) { v2 = v1; v1 = v.w; i1 = k + 3; }
        else v2 = fmaxf(v2, v.w);
    }
    #pragma unroll
    for (int off = 16; off > 0; off >>= 1) {
        float ov1 = __shfl_xor_sync(0xffffffffu, v1, off);
        int   oi1 = __shfl_xor_sync(0xffffffffu, i1, off);
        float ov2 = __shfl_xor_sync(0xffffffffu, v2, off);
        if (ov1 > v1 || (ov1 == v1 && oi1 < i1)) {
            v2 = fmaxf(v1, ov2);
            v1 = ov1; i1 = oi1;
        } else {
            v2 = fmaxf(v2, ov1);
        }
    }
    if (lane == 0) { wv1[wid] = v1; wi1[wid] = i1; wv2[wid] = v2; }
    __syncthreads();
    if (tid == 0) {
        float bv1 = wv1[0]; int bi1 = wi1[0]; float bv2 = wv2[0];
        #pragma unroll
        for (int w = 1; w < 8; w++) {
            if (wv1[w] > bv1 || (wv1[w] == bv1 && wi1[w] < bi1)) {
                bv2 = fmaxf(bv1, wv2[w]);
                bv1 = wv1[w]; bi1 = wi1[w];
            } else {
                bv2 = fmaxf(bv2, wv1[w]);
            }
        }
        g_rowt1v[r] = bv1;
        g_rowt1i[r] = bi1;
        g_rowt2v[r] = bv2;
    }
}

// ============================================================
// init / split
// ============================================================
__global__ void split_cb_kernel(const float* __restrict__ cb) {
    int r = blockIdx.x;
    const float4* c4 = (const float4*)(cb + (size_t)r * D_DIM);
    __half2* h0p = (__half2*)(g_cb0 + (size_t)r * D_DIM);
    __half2* h1p = (__half2*)(g_cb1 + (size_t)r * D_DIM);
    int tid = threadIdx.x;
    float4 v = c4[tid];
    __half2 a = __float22half2_rn(make_float2(v.x, v.y));
    __half2 b = __float22half2_rn(make_float2(v.z, v.w));
    h0p[tid * 2 + 0] = a;
    h0p[tid * 2 + 1] = b;
    h1p[tid * 2 + 0] = __floats2half2_rn(v.x - __low2float(a), v.y - __high2float(a));
    h1p[tid * 2 + 1] = __floats2half2_rn(v.z - __low2float(b), v.w - __high2float(b));
}

__global__ void init_kernel(const float* __restrict__ targets) {
    int r = blockIdx.x;
    int tid = threadIdx.x;
    int lane = tid & 31, wid = tid >> 5;
    __shared__ float wsum[8];

    const float4* t4 = (const float4*)(targets + (size_t)r * D_DIM);
    float4* r4 = (float4*)(g_resid + (size_t)r * D_DIM);
    __half2* h0p = (__half2*)(g_rh0 + (size_t)r * D_DIM);

    float4 v = t4[tid];
    r4[tid] = v;
    h0p[tid * 2 + 0] = __float22half2_rn(make_float2(v.x, v.y));
    h0p[tid * 2 + 1] = __float22half2_rn(make_float2(v.z, v.w));

    float local = v.x * v.x + v.y * v.y + v.z * v.z + v.w * v.w;
    #pragma unroll
    for (int off = 16; off > 0; off >>= 1)
        local += __shfl_xor_sync(0xffffffffu, local, off);
    if (lane == 0) wsum[wid] = local;
    __syncthreads();
    if (tid == 0) {
        float s = 0.f;
        #pragma unroll
        for (int w = 0; w < 8; w++) s += wsum[w];
        g_norm2[r] = s;
        g_active[r] = 1;
    }
}

// ============================================================
// update residual (exact fp32 chain)
// ============================================================
__global__ void update_kernel(const float* __restrict__ cb, int step, float decay) {
    int r = blockIdx.x;
    int tid = threadIdx.x;
    int lane = tid & 31, wid = tid >> 5;
    __shared__ int s_idx, s_act;
    __shared__ float wsum[8];

    if (tid == 0) {
        int i = g_choice[r];
        int act = g_active[r] && (sqrtf(g_norm2[r]) >= RES_TH);
        g_active[r] = act;
        g_indices[(size_t)r * L_STEPS + step] = act ? i : -1;
        s_idx = i;
        s_act = act;
    }
    __syncthreads();
    if (!s_act) return;

    int idx = s_idx;
    float4* r4 = (float4*)(g_resid + (size_t)r * D_DIM);
    const float4* c4 = (const float4*)(cb + (size_t)idx * D_DIM);

    float4 v = r4[tid];
    float4 c = c4[tid];
    v.x = __fsub_rn(v.x, __fmul_rn(decay, c.x));
    v.y = __fsub_rn(v.y, __fmul_rn(decay, c.y));
    v.z = __fsub_rn(v.z, __fmul_rn(decay, c.z));
    v.w = __fsub_rn(v.w, __fmul_rn(decay, c.w));
    r4[tid] = v;

    float local = v.x * v.x + v.y * v.y + v.z * v.z + v.w * v.w;
    #pragma unroll
    for (int off = 16; off > 0; off >>= 1)
        local += __shfl_xor_sync(0xffffffffu, local, off);
    if (lane == 0) wsum[wid] = local;
    __syncthreads();
    if (tid == 0) {
        float s = 0.f;
        #pragma unroll
        for (int w = 0; w < 8; w++) s += wsum[w];
        g_norm2[r] = s;
    }
}

// ============================================================
// finalize variants
// ============================================================
__global__ void out_both_f32(float* __restrict__ out) {
    int r = blockIdx.x;
    for (int c = threadIdx.x; c < D_DIM; c += 256)
        out[(size_t)B_ROWS * L_STEPS + (size_t)r * D_DIM + c] = g_resid[(size_t)r * D_DIM + c];
    if (threadIdx.x < L_STEPS)
        out[(size_t)r * L_STEPS + threadIdx.x] = (float)g_indices[(size_t)r * L_STEPS + threadIdx.x];
}
__global__ void out_idx_i32(int* __restrict__ out) {
    int i = blockIdx.x * 256 + threadIdx.x;
    if (i < B_ROWS * L_STEPS) out[i] = g_indices[i];
}
__global__ void out_res_f32(float* __restrict__ out) {
    int r = blockIdx.x;
    for (int c = threadIdx.x; c < D_DIM; c += 256)
        out[(size_t)r * D_DIM + c] = g_resid[(size_t)r * D_DIM + c];
}

// ============================================================
// host launcher
// ============================================================
extern "C" void kernel_launch(void* const* d_in, const int* in_sizes, int n_in,
                              void* d_out, int out_size) {
    const float* targets  = (const float*)d_in[0];
    const float* codebook = (const float*)d_in[1];

    cudaFuncSetAttribute(gemm0_kernel,
                         cudaFuncAttributeMaxDynamicSharedMemorySize, SMEM_TOTAL);
    cudaFuncSetAttribute(gram_kernel,
                         cudaFuncAttributeMaxDynamicSharedMemorySize, GSMEM);

    split_cb_kernel<<<K_CB, 256>>>(codebook);
    init_kernel<<<B_ROWS, 256>>>(targets);

    {   // Gram matrix G = cb @ cb^T (fp32, 3-pass fp16-split)
        dim3 grid(K_CB / 128, K_CB / 128);
        gram_kernel<<<grid, 256, GSMEM>>>();
    }
    {   // initial scores = targets @ cb^T + per-tile top-2
        dim3 grid(B_ROWS / BM, K_CB / BN);
        gemm0_kernel<<<grid, 256, SMEM_TOTAL>>>();
    }

    for (int s = 0; s < L_STEPS; s++) {
        if (s == 0) select_tiles_kernel<<<B_ROWS / 8, 256>>>();
        else        select_rows_kernel<<<B_ROWS / 256, 256>>>();
        refine_kernel<<<128, 256>>>(codebook);
        float decay = (float)pow(0.9, (double)s);
        update_kernel<<<B_ROWS, 256>>>(codebook, s, decay);
        if (s + 1 < L_STEPS)
            scores_update_kernel<<<B_ROWS, 256>>>(decay);
    }

    if (out_size == B_ROWS * L_STEPS) {
        out_idx_i32<<<(B_ROWS * L_STEPS + 255) / 256, 256>>>((int*)d_out);
    } else if (out_size == B_ROWS * D_DIM) {
        out_res_f32<<<B_ROWS, 256>>>((float*)d_out);
    } else {
        out_both_f32<<<B_ROWS, 256>>>((float*)d_out);
    }
}

// round 9
// speedup vs baseline: 3.8508x; 1.1343x over previous
#include <cuda_runtime.h>
#include <cuda_fp16.h>
#include <cstdint>
#include <math.h>

// ============================================================
// Problem constants
// ============================================================
#define B_ROWS 8192
#define D_DIM  1024
#define K_CB   4096
#define L_STEPS 8
#define RES_TH 1e-3f
#define THR    0.40f

// GEMM tiling: CTA 256x128, warp tile 64x64
#define BM 256
#define BN 128
#define BK 64
#define NT    (K_CB / BN)     // 32
#define NKCH  (D_DIM / BK)    // 16
#define NSTAGE 4
#define A_BYTES (BM * BK * 2)
#define B_BYTES (BN * BK * 2)
#define STAGE_BYTES (A_BYTES + B_BYTES)        // 49152
#define SMEM_TOTAL  (NSTAGE * STAGE_BYTES)     // 196608

// ============================================================
// Device scratch — every array <= 32 MB
// ============================================================
__device__ __align__(128) float  g_resid[B_ROWS * D_DIM];            // 32 MB
__device__ __align__(128) __half g_rh0[B_ROWS * D_DIM];              // 16 MB
__device__ __align__(128) __half g_cb0[K_CB * D_DIM];                // 8 MB
#define SC_CHUNK_ROWS 2048
__device__ __align__(128) float g_sc0[SC_CHUNK_ROWS * K_CB];         // 32 MB x4
__device__ __align__(128) float g_sc1[SC_CHUNK_ROWS * K_CB];
__device__ __align__(128) float g_sc2[SC_CHUNK_ROWS * K_CB];
__device__ __align__(128) float g_sc3[SC_CHUNK_ROWS * K_CB];
__device__ __align__(128) float g_G0[SC_CHUNK_ROWS * K_CB];          // 32 MB x2
__device__ __align__(128) float g_G1[SC_CHUNK_ROWS * K_CB];

__device__ float g_t1v[B_ROWS * NT];
__device__ int   g_t1i[B_ROWS * NT];
__device__ float g_t2v[B_ROWS * NT];
__device__ int   g_t2i[B_ROWS * NT];
__device__ float g_rowt1v[B_ROWS];
__device__ int   g_rowt1i[B_ROWS];
__device__ float g_rowt2v[B_ROWS];
__device__ float g_norm2[B_ROWS];
__device__ int   g_active[B_ROWS];
__device__ int   g_indices[B_ROWS * L_STEPS];
__device__ int   g_choice[B_ROWS];
__device__ int   g_flagcnt;
__device__ int   g_flaglist[B_ROWS];

__device__ __forceinline__ float* score_row(int r) {
    int c = r >> 11;
    float* b = (c == 0) ? g_sc0 : (c == 1) ? g_sc1 : (c == 2) ? g_sc2 : g_sc3;
    return b + (size_t)(r & (SC_CHUNK_ROWS - 1)) * K_CB;
}
__device__ __forceinline__ float* G_row(int k) {
    float* b = (k >> 11) ? g_G1 : g_G0;
    return b + (size_t)(k & (SC_CHUNK_ROWS - 1)) * K_CB;
}

// ============================================================
// PTX helpers
// ============================================================
__device__ __forceinline__ uint32_t smem_u32(const void* p) {
    uint32_t a;
    asm("{ .reg .u64 t; cvta.to.shared.u64 t, %1; cvt.u32.u64 %0, t; }"
        : "=r"(a) : "l"(p));
    return a;
}
__device__ __forceinline__ void cp16(uint32_t s, const void* g) {
    asm volatile("cp.async.cg.shared.global [%0], [%1], 16;" :: "r"(s), "l"(g));
}
#define CP_COMMIT() asm volatile("cp.async.commit_group;" ::: "memory")
#define CP_WAIT(n)  asm volatile("cp.async.wait_group %0;" :: "n"(n) : "memory")

__device__ __forceinline__ void ldsm4(uint32_t* r, uint32_t addr) {
    asm volatile("ldmatrix.sync.aligned.m8n8.x4.shared.b16 {%0,%1,%2,%3}, [%4];"
        : "=r"(r[0]), "=r"(r[1]), "=r"(r[2]), "=r"(r[3]) : "r"(addr));
}
__device__ __forceinline__ void mma16816(float* c, const uint32_t* a, const uint32_t* b) {
    asm volatile(
        "mma.sync.aligned.m16n8k16.row.col.f32.f16.f16.f32 "
        "{%0,%1,%2,%3}, {%4,%5,%6,%7}, {%8,%9}, {%0,%1,%2,%3};"
        : "+f"(c[0]), "+f"(c[1]), "+f"(c[2]), "+f"(c[3])
        : "r"(a[0]), "r"(a[1]), "r"(a[2]), "r"(a[3]), "r"(b[0]), "r"(b[1]));
}
__device__ __forceinline__ uint32_t sw_addr(uint32_t base, int row, int unit) {
    return base + (uint32_t)(row * 128) + (uint32_t)((unit ^ (row & 7)) << 4);
}

struct Top2 { float v1; int i1; float v2; int i2; };
__device__ __forceinline__ void t2_insert(Top2& t, float v, int c) {
    if (v > t.v1 || (v == t.v1 && c < t.i1)) {
        t.v2 = t.v1; t.i2 = t.i1; t.v1 = v; t.i1 = c;
    } else if (v > t.v2 || (v == t.v2 && c < t.i2)) {
        t.v2 = v; t.i2 = c;
    }
}
__device__ __forceinline__ void t2_merge(Top2& a, const Top2& b) {
    if (b.v1 > a.v1 || (b.v1 == a.v1 && b.i1 < a.i1)) {
        if (a.v1 > b.v2 || (a.v1 == b.v2 && a.i1 < b.i2)) { a.v2 = a.v1; a.i2 = a.i1; }
        else { a.v2 = b.v2; a.i2 = b.i2; }
        a.v1 = b.v1; a.i1 = b.i1;
    } else {
        if (b.v1 > a.v2 || (b.v1 == a.v2 && b.i1 < a.i2)) { a.v2 = b.v1; a.i2 = b.i1; }
    }
}

// ============================================================
// Unified GEMM: MODE 0 -> scores + per-tile top-2; MODE 1 -> Gram fp32
// grid (Mrows/256, 32), 256 thr, 8 warps (4M x 2N), warp tile 64x64
// NOTE: BM=256 divides SC_CHUNK_ROWS=2048, so one CTA tile lies
// entirely within one chunk -> single base pointer per CTA.
// ============================================================
__device__ __forceinline__ void fill_stage(uint32_t st, const __half* Ag,
                                           int tileM, int tileN, int kc, int tid) {
    const __half* a0 = Ag + ((size_t)tileM * BM) * D_DIM + kc * BK;
    const __half* b0 = g_cb0 + ((size_t)tileN * BN) * D_DIM + kc * BK;
    #pragma unroll
    for (int i = 0; i < 8; i++) {
        int c = tid + i * 256;
        int row = c >> 3, u = c & 7;
        uint32_t sw = (uint32_t)(row * 128) + (uint32_t)((u ^ (row & 7)) << 4);
        cp16(st + sw, a0 + (size_t)row * D_DIM + (u << 3));
    }
    #pragma unroll
    for (int i = 0; i < 4; i++) {
        int c = tid + i * 256;
        int row = c >> 3, u = c & 7;
        uint32_t sw = (uint32_t)(row * 128) + (uint32_t)((u ^ (row & 7)) << 4);
        cp16(st + A_BYTES + sw, b0 + (size_t)row * D_DIM + (u << 3));
    }
}

template <int MODE>
__global__ void __launch_bounds__(256, 1) gemm_kernel() {
    extern __shared__ char smem[];
    uint32_t sb = smem_u32(smem);
    const int tid = threadIdx.x;
    const int tileM = blockIdx.x, tileN = blockIdx.y;
    const int wid = tid >> 5, lane = tid & 31;
    const int warpM = wid >> 1, warpN = wid & 1;
    const int grp = lane >> 2, qc = lane & 3;

    const __half* Ag = (MODE == 0) ? g_rh0 : g_cb0;

    if (MODE == 0 && tileM == 0 && tileN == 0 && tid == 0) g_flagcnt = 0;

    float acc[4][8][4];
    #pragma unroll
    for (int mi = 0; mi < 4; mi++)
        #pragma unroll
        for (int ni = 0; ni < 8; ni++)
            #pragma unroll
            for (int j = 0; j < 4; j++) acc[mi][ni][j] = 0.f;

    fill_stage(sb, Ag, tileM, tileN, 0, tid);                      CP_COMMIT();
    fill_stage(sb + STAGE_BYTES, Ag, tileM, tileN, 1, tid);        CP_COMMIT();
    fill_stage(sb + 2 * STAGE_BYTES, Ag, tileM, tileN, 2, tid);    CP_COMMIT();

    #pragma unroll 1
    for (int kc = 0; kc < NKCH; kc++) {
        if (kc < NKCH - 2)      { CP_WAIT(2); }
        else if (kc == NKCH - 2){ CP_WAIT(1); }
        else                    { CP_WAIT(0); }
        __syncthreads();
        if (kc + 3 < NKCH) {
            fill_stage(sb + (uint32_t)(((kc + 3) % NSTAGE) * STAGE_BYTES),
                       Ag, tileM, tileN, kc + 3, tid);
            CP_COMMIT();
        }
        uint32_t st = sb + (uint32_t)((kc % NSTAGE) * STAGE_BYTES);
        uint32_t aBase = st, bBase = st + A_BYTES;
        const int aRowB = warpM * 64 + (lane & 15);
        const int bRowB = warpN * 64 + ((lane >> 4) << 3) + (lane & 7);
        #pragma unroll
        for (int ks = 0; ks < 4; ks++) {
            const int u = ks * 2;
            const int aU = u + (lane >> 4);
            const int bU = u + ((lane >> 3) & 1);
            uint32_t af[4][4], bf[8][2];
            #pragma unroll
            for (int mi = 0; mi < 4; mi++)
                ldsm4(af[mi], sw_addr(aBase, aRowB + mi * 16, aU));
            #pragma unroll
            for (int nb = 0; nb < 4; nb++) {
                uint32_t r[4];
                ldsm4(r, sw_addr(bBase, bRowB + nb * 16, bU));
                bf[nb * 2 + 0][0] = r[0]; bf[nb * 2 + 0][1] = r[1];
                bf[nb * 2 + 1][0] = r[2]; bf[nb * 2 + 1][1] = r[3];
            }
            #pragma unroll
            for (int mi = 0; mi < 4; mi++)
                #pragma unroll
                for (int ni = 0; ni < 8; ni++)
                    mma16816(acc[mi][ni], af[mi], bf[ni]);
        }
    }

    // store result rows — single base pointer per CTA (no per-element chunk select)
    {
        float* outb = (MODE == 0) ? score_row(tileM * BM) : G_row(tileM * BM);
        #pragma unroll
        for (int mi = 0; mi < 4; mi++) {
            #pragma unroll
            for (int ni = 0; ni < 8; ni++) {
                int lr = warpM * 64 + mi * 16 + grp;
                int c0 = tileN * BN + warpN * 64 + ni * 8 + qc * 2;
                *(float2*)&outb[(size_t)lr * K_CB + c0] =
                    make_float2(acc[mi][ni][0], acc[mi][ni][1]);
                *(float2*)&outb[(size_t)(lr + 8) * K_CB + c0] =
                    make_float2(acc[mi][ni][2], acc[mi][ni][3]);
            }
        }
    }

    if (MODE == 1) return;

    __syncthreads();
    float* sv1 = (float*)smem;
    int*   si1 = (int*)(smem + 2048);
    float* sv2 = (float*)(smem + 4096);
    int*   si2 = (int*)(smem + 6144);

    #pragma unroll
    for (int mi = 0; mi < 4; mi++) {
        Top2 lo = {-3.4e38f, 0x7fffffff, -3.4e38f, 0x7fffffff};
        Top2 hi = {-3.4e38f, 0x7fffffff, -3.4e38f, 0x7fffffff};
        #pragma unroll
        for (int ni = 0; ni < 8; ni++) {
            #pragma unroll
            for (int j = 0; j < 2; j++) {
                int c = warpN * 64 + ni * 8 + qc * 2 + j;
                t2_insert(lo, acc[mi][ni][j], c);
                t2_insert(hi, acc[mi][ni][2 + j], c);
            }
        }
        #pragma unroll
        for (int off = 1; off < 4; off <<= 1) {
            Top2 o;
            o.v1 = __shfl_xor_sync(0xffffffffu, lo.v1, off);
            o.i1 = __shfl_xor_sync(0xffffffffu, lo.i1, off);
            o.v2 = __shfl_xor_sync(0xffffffffu, lo.v2, off);
            o.i2 = __shfl_xor_sync(0xffffffffu, lo.i2, off);
            t2_merge(lo, o);
            o.v1 = __shfl_xor_sync(0xffffffffu, hi.v1, off);
            o.i1 = __shfl_xor_sync(0xffffffffu, hi.i1, off);
            o.v2 = __shfl_xor_sync(0xffffffffu, hi.v2, off);
            o.i2 = __shfl_xor_sync(0xffffffffu, hi.i2, off);
            t2_merge(hi, o);
        }
        if (qc == 0) {
            int rLo = warpM * 64 + mi * 16 + grp;
            sv1[rLo * 2 + warpN] = lo.v1;  si1[rLo * 2 + warpN] = lo.i1;
            sv2[rLo * 2 + warpN] = lo.v2;  si2[rLo * 2 + warpN] = lo.i2;
            int rHi = rLo + 8;
            sv1[rHi * 2 + warpN] = hi.v1;  si1[rHi * 2 + warpN] = hi.i1;
            sv2[rHi * 2 + warpN] = hi.v2;  si2[rHi * 2 + warpN] = hi.i2;
        }
    }
    __syncthreads();
    {
        Top2 t = {sv1[tid * 2], si1[tid * 2], sv2[tid * 2], si2[tid * 2]};
        Top2 o = {sv1[tid * 2 + 1], si1[tid * 2 + 1],
                  sv2[tid * 2 + 1], si2[tid * 2 + 1]};
        t2_merge(t, o);
        size_t oo = (size_t)(tileM * BM + tid) * NT + tileN;
        g_t1v[oo] = t.v1;  g_t1i[oo] = tileN * BN + t.i1;
        g_t2v[oo] = t.v2;  g_t2i[oo] = tileN * BN + t.i2;
    }
}

// ============================================================
// select step 0 / steps >= 1
// ============================================================
__global__ void select_tiles_kernel() {
    int tid = threadIdx.x, lane = tid & 31, wid = tid >> 5;
    int r = blockIdx.x * 8 + wid;
    size_t o = (size_t)r * NT + lane;
    float v1 = g_t1v[o];
    int   i1 = g_t1i[o];
    float v2 = g_t2v[o];
    #pragma unroll
    for (int off = 16; off > 0; off >>= 1) {
        float ov1 = __shfl_xor_sync(0xffffffffu, v1, off);
        int   oi1 = __shfl_xor_sync(0xffffffffu, i1, off);
        float ov2 = __shfl_xor_sync(0xffffffffu, v2, off);
        if (ov1 > v1 || (ov1 == v1 && oi1 < i1)) {
            v2 = fmaxf(ov2, v1);
            v1 = ov1; i1 = oi1;
        } else {
            v2 = fmaxf(v2, ov1);
        }
    }
    if (lane == 0) {
        g_choice[r] = i1;
        g_rowt1v[r] = v1;
        if (v1 - v2 < THR) {
            int p = atomicAdd(&g_flagcnt, 1);
            g_flaglist[p] = r;
        }
    }
}

__global__ void select_rows_kernel() {
    int r = blockIdx.x * 256 + threadIdx.x;
    if (r >= B_ROWS) return;
    g_choice[r] = g_rowt1i[r];
    if (g_rowt1v[r] - g_rowt2v[r] < THR) {
        int p = atomicAdd(&g_flagcnt, 1);
        g_flaglist[p] = r;
    }
}

// ============================================================
// refine: flagged rows, exact Kahan dots on candidates
// ============================================================
__global__ void refine_kernel(const float* __restrict__ cb) {
    __shared__ float sres[D_DIM];
    __shared__ int scand[128];
    __shared__ int scnt;
    __shared__ float sbv[8];
    __shared__ int   sbi[8];
    int tid = threadIdx.x, lane = tid & 31, wid = tid >> 5;
    int cnt = *(volatile int*)&g_flagcnt;

    for (int f = blockIdx.x; f < cnt; f += gridDim.x) {
        int r = g_flaglist[f];
        ((float4*)sres)[tid] = ((const float4*)(g_resid + (size_t)r * D_DIM))[tid];
        if (tid == 0) scnt = 0;
        __syncthreads();

        float thr = g_rowt1v[r] - THR;
        const float4* sc = (const float4*)score_row(r);
        #pragma unroll
        for (int i = 0; i < 4; i++) {
            int e = i * 256 + tid;
            float4 v = sc[e];
            int k = e * 4;
            if (v.x > thr) { int p = atomicAdd(&scnt, 1); if (p < 128) scand[p] = k; }
            if (v.y > thr) { int p = atomicAdd(&scnt, 1); if (p < 128) scand[p] = k + 1; }
            if (v.z > thr) { int p = atomicAdd(&scnt, 1); if (p < 128) scand[p] = k + 2; }
            if (v.w > thr) { int p = atomicAdd(&scnt, 1); if (p < 128) scand[p] = k + 3; }
        }
        __syncthreads();
        int nc = min(scnt, 128);

        float bv = -3.4e38f; int bi = 0x7fffffff;
        for (int c = wid; c < nc; c += 8) {
            int k = scand[c];
            const float* cbr = cb + (size_t)k * D_DIM;
            float s = 0.f, comp = 0.f;
            for (int e = lane; e < D_DIM; e += 32) {
                float prod = sres[e] * cbr[e];
                float y = prod - comp;
                float t = s + y;
                comp = (t - s) - y;
                s = t;
            }
            #pragma unroll
            for (int off = 16; off > 0; off >>= 1)
                s += __shfl_xor_sync(0xffffffffu, s, off);
            if (s > bv || (s == bv && k < bi)) { bv = s; bi = k; }
        }
        if (lane == 0) { sbv[wid] = bv; sbi[wid] = bi; }
        __syncthreads();
        if (tid == 0) {
            float v = sbv[0]; int i = sbi[0];
            #pragma unroll
            for (int w = 1; w < 8; w++)
                if (sbv[w] > v || (sbv[w] == v && sbi[w] < i)) { v = sbv[w]; i = sbi[w]; }
            g_choice[r] = i;
        }
        __syncthreads();
    }
}

// ============================================================
// fused step: gate + index write + residual update + norm +
// (if not last) score recurrence + next-step per-row top-2
// ============================================================
__global__ void step_kernel(const float* __restrict__ cb, int step, float decay,
                            int last) {
    int r = blockIdx.x;
    int tid = threadIdx.x, lane = tid & 31, wid = tid >> 5;
    __shared__ int s_idx, s_act;
    __shared__ float wsum[8];
    __shared__ float wv1[8]; __shared__ int wi1[8]; __shared__ float wv2[8];

    if (r == 0 && tid == 0) g_flagcnt = 0;

    if (tid == 0) {
        int i = g_choice[r];
        int act = g_active[r] && (sqrtf(g_norm2[r]) >= RES_TH);
        g_active[r] = act;
        g_indices[(size_t)r * L_STEPS + step] = act ? i : -1;
        s_idx = i;
        s_act = act;
    }
    __syncthreads();
    if (!s_act) return;

    int idx = s_idx;

    // --- residual update (exact fp32 chain) ---
    {
        float4* r4 = (float4*)(g_resid + (size_t)r * D_DIM);
        const float4* c4 = (const float4*)(cb + (size_t)idx * D_DIM);
        float4 v = r4[tid];
        float4 c = c4[tid];
        v.x = __fsub_rn(v.x, __fmul_rn(decay, c.x));
        v.y = __fsub_rn(v.y, __fmul_rn(decay, c.y));
        v.z = __fsub_rn(v.z, __fmul_rn(decay, c.z));
        v.w = __fsub_rn(v.w, __fmul_rn(decay, c.w));
        r4[tid] = v;
        float local = v.x * v.x + v.y * v.y + v.z * v.z + v.w * v.w;
        #pragma unroll
        for (int off = 16; off > 0; off >>= 1)
            local += __shfl_xor_sync(0xffffffffu, local, off);
        if (lane == 0) wsum[wid] = local;
    }
    __syncthreads();
    if (tid == 0) {
        float s = 0.f;
        #pragma unroll
        for (int w = 0; w < 8; w++) s += wsum[w];
        g_norm2[r] = s;
    }

    if (last) return;

    // --- score recurrence + next-step top-2 ---
    const float4* G4 = (const float4*)G_row(idx);
    float4* sc = (float4*)score_row(r);

    float v1 = -3.4e38f; int i1 = 0x7fffffff; float v2 = -3.4e38f;
    #pragma unroll
    for (int i = 0; i < 4; i++) {
        int e = i * 256 + tid;
        float4 v = sc[e];
        float4 g = G4[e];
        v.x -= decay * g.x;
        v.y -= decay * g.y;
        v.z -= decay * g.z;
        v.w -= decay * g.w;
        sc[e] = v;
        int k = e * 4;
        if (v.x > v1 || (v.x == v1 && k < i1)) { v2 = v1; v1 = v.x; i1 = k; }
        else v2 = fmaxf(v2, v.x);
        if (v.y > v1 || (v.y == v1 && k + 1 < i1)) { v2 = v1; v1 = v.y; i1 = k + 1; }
        else v2 = fmaxf(v2, v.y);
        if (v.z > v1 || (v.z == v1 && k + 2 < i1)) { v2 = v1; v1 = v.z; i1 = k + 2; }
        else v2 = fmaxf(v2, v.z);
        if (v.w > v1 || (v.w == v1 && k + 3 < i1)) { v2 = v1; v1 = v.w; i1 = k + 3; }
        else v2 = fmaxf(v2, v.w);
    }
    #pragma unroll
    for (int off = 16; off > 0; off >>= 1) {
        float ov1 = __shfl_xor_sync(0xffffffffu, v1, off);
        int   oi1 = __shfl_xor_sync(0xffffffffu, i1, off);
        float ov2 = __shfl_xor_sync(0xffffffffu, v2, off);
        if (ov1 > v1 || (ov1 == v1 && oi1 < i1)) {
            v2 = fmaxf(v1, ov2);
            v1 = ov1; i1 = oi1;
        } else {
            v2 = fmaxf(v2, ov1);
        }
    }
    if (lane == 0) { wv1[wid] = v1; wi1[wid] = i1; wv2[wid] = v2; }
    __syncthreads();
    if (tid == 0) {
        float bv1 = wv1[0]; int bi1 = wi1[0]; float bv2 = wv2[0];
        #pragma unroll
        for (int w = 1; w < 8; w++) {
            if (wv1[w] > bv1 || (wv1[w] == bv1 && wi1[w] < bi1)) {
                bv2 = fmaxf(bv1, wv2[w]);
                bv1 = wv1[w]; bi1 = wi1[w];
            } else {
                bv2 = fmaxf(bv2, wv1[w]);
            }
        }
        g_rowt1v[r] = bv1;
        g_rowt1i[r] = bi1;
        g_rowt2v[r] = bv2;
    }
}

// ============================================================
// init / split
// ============================================================
__global__ void split_cb_kernel(const float* __restrict__ cb) {
    int r = blockIdx.x;
    const float4* c4 = (const float4*)(cb + (size_t)r * D_DIM);
    __half2* h0p = (__half2*)(g_cb0 + (size_t)r * D_DIM);
    int tid = threadIdx.x;
    float4 v = c4[tid];
    h0p[tid * 2 + 0] = __float22half2_rn(make_float2(v.x, v.y));
    h0p[tid * 2 + 1] = __float22half2_rn(make_float2(v.z, v.w));
}

__global__ void init_kernel(const float* __restrict__ targets) {
    int r = blockIdx.x;
    int tid = threadIdx.x;
    int lane = tid & 31, wid = tid >> 5;
    __shared__ float wsum[8];

    const float4* t4 = (const float4*)(targets + (size_t)r * D_DIM);
    float4* r4 = (float4*)(g_resid + (size_t)r * D_DIM);
    __half2* h0p = (__half2*)(g_rh0 + (size_t)r * D_DIM);

    float4 v = t4[tid];
    r4[tid] = v;
    h0p[tid * 2 + 0] = __float22half2_rn(make_float2(v.x, v.y));
    h0p[tid * 2 + 1] = __float22half2_rn(make_float2(v.z, v.w));

    float local = v.x * v.x + v.y * v.y + v.z * v.z + v.w * v.w;
    #pragma unroll
    for (int off = 16; off > 0; off >>= 1)
        local += __shfl_xor_sync(0xffffffffu, local, off);
    if (lane == 0) wsum[wid] = local;
    __syncthreads();
    if (tid == 0) {
        float s = 0.f;
        #pragma unroll
        for (int w = 0; w < 8; w++) s += wsum[w];
        g_norm2[r] = s;
        g_active[r] = 1;
    }
}

// ============================================================
// finalize variants
// ============================================================
__global__ void out_both_f32(float* __restrict__ out) {
    int r = blockIdx.x;
    for (int c = threadIdx.x; c < D_DIM; c += 256)
        out[(size_t)B_ROWS * L_STEPS + (size_t)r * D_DIM + c] = g_resid[(size_t)r * D_DIM + c];
    if (threadIdx.x < L_STEPS)
        out[(size_t)r * L_STEPS + threadIdx.x] = (float)g_indices[(size_t)r * L_STEPS + threadIdx.x];
}
__global__ void out_idx_i32(int* __restrict__ out) {
    int i = blockIdx.x * 256 + threadIdx.x;
    if (i < B_ROWS * L_STEPS) out[i] = g_indices[i];
}
__global__ void out_res_f32(float* __restrict__ out) {
    int r = blockIdx.x;
    for (int c = threadIdx.x; c < D_DIM; c += 256)
        out[(size_t)r * D_DIM + c] = g_resid[(size_t)r * D_DIM + c];
}

// ============================================================
// host launcher
// ============================================================
extern "C" void kernel_launch(void* const* d_in, const int* in_sizes, int n_in,
                              void* d_out, int out_size) {
    const float* targets  = (const float*)d_in[0];
    const float* codebook = (const float*)d_in[1];

    cudaFuncSetAttribute(gemm_kernel<0>,
                         cudaFuncAttributeMaxDynamicSharedMemorySize, SMEM_TOTAL);
    cudaFuncSetAttribute(gemm_kernel<1>,
                         cudaFuncAttributeMaxDynamicSharedMemorySize, SMEM_TOTAL);

    split_cb_kernel<<<K_CB, 256>>>(codebook);
    init_kernel<<<B_ROWS, 256>>>(targets);

    {   // Gram matrix G = cb @ cb^T (fp32 out, 1-plane fp16)
        dim3 grid(K_CB / BM, K_CB / BN);
        gemm_kernel<1><<<grid, 256, SMEM_TOTAL>>>();
    }
    {   // initial scores = targets @ cb^T + per-tile top-2
        dim3 grid(B_ROWS / BM, K_CB / BN);
        gemm_kernel<0><<<grid, 256, SMEM_TOTAL>>>();
    }

    for (int s = 0; s < L_STEPS; s++) {
        if (s == 0) select_tiles_kernel<<<B_ROWS / 8, 256>>>();
        else        select_rows_kernel<<<B_ROWS / 256, 256>>>();
        refine_kernel<<<128, 256>>>(codebook);
        float decay = (float)pow(0.9, (double)s);
        step_kernel<<<B_ROWS, 256>>>(codebook, s, decay, s + 1 == L_STEPS);
    }

    if (out_size == B_ROWS * L_STEPS) {
        out_idx_i32<<<(B_ROWS * L_STEPS + 255) / 256, 256>>>((int*)d_out);
    } else if (out_size == B_ROWS * D_DIM) {
        out_res_f32<<<B_ROWS, 256>>>((float*)d_out);
    } else {
        out_both_f32<<<B_ROWS, 256>>>((float*)d_out);
    }
}

// round 10
// speedup vs baseline: 3.9232x; 1.0188x over previous
#include <cuda_runtime.h>
#include <cuda_fp16.h>
#include <cstdint>
#include <math.h>

// ============================================================
// Problem constants
// ============================================================
#define B_ROWS 8192
#define D_DIM  1024
#define K_CB   4096
#define L_STEPS 8
#define RES_TH 1e-3f
#define THR    0.40f

// GEMM tiling: CTA 256x128, 512 threads, 16 warps (4M x 4N), warp tile 64x32
#define BM 256
#define BN 128
#define BK 64
#define NT    (K_CB / BN)     // 32
#define NKCH  (D_DIM / BK)    // 16
#define NSTAGE 4
#define A_BYTES (BM * BK * 2)
#define B_BYTES (BN * BK * 2)
#define STAGE_BYTES (A_BYTES + B_BYTES)        // 49152
#define SMEM_TOTAL  (NSTAGE * STAGE_BYTES)     // 196608

// ============================================================
// Device scratch — every array <= 32 MB
// ============================================================
__device__ __align__(128) float  g_resid[B_ROWS * D_DIM];            // 32 MB
__device__ __align__(128) __half g_rh0[B_ROWS * D_DIM];              // 16 MB
__device__ __align__(128) __half g_cb0[K_CB * D_DIM];                // 8 MB
#define SC_CHUNK_ROWS 2048
__device__ __align__(128) float g_sc0[SC_CHUNK_ROWS * K_CB];         // 32 MB x4
__device__ __align__(128) float g_sc1[SC_CHUNK_ROWS * K_CB];
__device__ __align__(128) float g_sc2[SC_CHUNK_ROWS * K_CB];
__device__ __align__(128) float g_sc3[SC_CHUNK_ROWS * K_CB];
__device__ __align__(128) float g_G0[SC_CHUNK_ROWS * K_CB];          // 32 MB x2
__device__ __align__(128) float g_G1[SC_CHUNK_ROWS * K_CB];

__device__ float g_t1v[B_ROWS * NT];
__device__ int   g_t1i[B_ROWS * NT];
__device__ float g_t2v[B_ROWS * NT];
__device__ int   g_t2i[B_ROWS * NT];
__device__ float g_rowt1v[B_ROWS];
__device__ int   g_rowt1i[B_ROWS];
__device__ float g_rowt2v[B_ROWS];
__device__ float g_norm2[B_ROWS];
__device__ int   g_active[B_ROWS];
__device__ int   g_indices[B_ROWS * L_STEPS];
__device__ int   g_choice[B_ROWS];
__device__ int   g_flagcnt;
__device__ int   g_flaglist[B_ROWS];

__device__ __forceinline__ float* score_row(int r) {
    int c = r >> 11;
    float* b = (c == 0) ? g_sc0 : (c == 1) ? g_sc1 : (c == 2) ? g_sc2 : g_sc3;
    return b + (size_t)(r & (SC_CHUNK_ROWS - 1)) * K_CB;
}
__device__ __forceinline__ float* G_row(int k) {
    float* b = (k >> 11) ? g_G1 : g_G0;
    return b + (size_t)(k & (SC_CHUNK_ROWS - 1)) * K_CB;
}

// ============================================================
// PTX helpers
// ============================================================
__device__ __forceinline__ uint32_t smem_u32(const void* p) {
    uint32_t a;
    asm("{ .reg .u64 t; cvta.to.shared.u64 t, %1; cvt.u32.u64 %0, t; }"
        : "=r"(a) : "l"(p));
    return a;
}
__device__ __forceinline__ void cp16(uint32_t s, const void* g) {
    asm volatile("cp.async.cg.shared.global [%0], [%1], 16;" :: "r"(s), "l"(g));
}
#define CP_COMMIT() asm volatile("cp.async.commit_group;" ::: "memory")
#define CP_WAIT(n)  asm volatile("cp.async.wait_group %0;" :: "n"(n) : "memory")

__device__ __forceinline__ void ldsm4(uint32_t* r, uint32_t addr) {
    asm volatile("ldmatrix.sync.aligned.m8n8.x4.shared.b16 {%0,%1,%2,%3}, [%4];"
        : "=r"(r[0]), "=r"(r[1]), "=r"(r[2]), "=r"(r[3]) : "r"(addr));
}
__device__ __forceinline__ void mma16816(float* c, const uint32_t* a, const uint32_t* b) {
    asm volatile(
        "mma.sync.aligned.m16n8k16.row.col.f32.f16.f16.f32 "
        "{%0,%1,%2,%3}, {%4,%5,%6,%7}, {%8,%9}, {%0,%1,%2,%3};"
        : "+f"(c[0]), "+f"(c[1]), "+f"(c[2]), "+f"(c[3])
        : "r"(a[0]), "r"(a[1]), "r"(a[2]), "r"(a[3]), "r"(b[0]), "r"(b[1]));
}
__device__ __forceinline__ uint32_t sw_addr(uint32_t base, int row, int unit) {
    return base + (uint32_t)(row * 128) + (uint32_t)((unit ^ (row & 7)) << 4);
}

struct Top2 { float v1; int i1; float v2; int i2; };
__device__ __forceinline__ void t2_insert(Top2& t, float v, int c) {
    if (v > t.v1 || (v == t.v1 && c < t.i1)) {
        t.v2 = t.v1; t.i2 = t.i1; t.v1 = v; t.i1 = c;
    } else if (v > t.v2 || (v == t.v2 && c < t.i2)) {
        t.v2 = v; t.i2 = c;
    }
}
__device__ __forceinline__ void t2_merge(Top2& a, const Top2& b) {
    if (b.v1 > a.v1 || (b.v1 == a.v1 && b.i1 < a.i1)) {
        if (a.v1 > b.v2 || (a.v1 == b.v2 && a.i1 < b.i2)) { a.v2 = a.v1; a.i2 = a.i1; }
        else { a.v2 = b.v2; a.i2 = b.i2; }
        a.v1 = b.v1; a.i1 = b.i1;
    } else {
        if (b.v1 > a.v2 || (b.v1 == a.v2 && b.i1 < a.i2)) { a.v2 = b.v1; a.i2 = b.i1; }
    }
}

// ============================================================
// Unified GEMM: MODE 0 -> scores + per-tile top-2; MODE 1 -> Gram fp32
// grid (Mrows/256, 32), 512 thr, 16 warps (4M x 4N), warp tile 64x32
// ============================================================
__device__ __forceinline__ void fill_stage(uint32_t st, const __half* Ag,
                                           int tileM, int tileN, int kc, int tid) {
    const __half* a0 = Ag + ((size_t)tileM * BM) * D_DIM + kc * BK;
    const __half* b0 = g_cb0 + ((size_t)tileN * BN) * D_DIM + kc * BK;
    #pragma unroll
    for (int i = 0; i < 4; i++) {   // A: 2048 chunks / 512 thr
        int c = tid + i * 512;
        int row = c >> 3, u = c & 7;
        uint32_t sw = (uint32_t)(row * 128) + (uint32_t)((u ^ (row & 7)) << 4);
        cp16(st + sw, a0 + (size_t)row * D_DIM + (u << 3));
    }
    #pragma unroll
    for (int i = 0; i < 2; i++) {   // B: 1024 chunks / 512 thr
        int c = tid + i * 512;
        int row = c >> 3, u = c & 7;
        uint32_t sw = (uint32_t)(row * 128) + (uint32_t)((u ^ (row & 7)) << 4);
        cp16(st + A_BYTES + sw, b0 + (size_t)row * D_DIM + (u << 3));
    }
}

template <int MODE>
__global__ void __launch_bounds__(512, 1) gemm_kernel() {
    extern __shared__ char smem[];
    uint32_t sb = smem_u32(smem);
    const int tid = threadIdx.x;
    const int tileM = blockIdx.x, tileN = blockIdx.y;
    const int wid = tid >> 5, lane = tid & 31;
    const int warpM = wid >> 2, warpN = wid & 3;
    const int grp = lane >> 2, qc = lane & 3;

    const __half* Ag = (MODE == 0) ? g_rh0 : g_cb0;

    if (MODE == 0 && tileM == 0 && tileN == 0 && tid == 0) g_flagcnt = 0;

    float acc[4][4][4];
    #pragma unroll
    for (int mi = 0; mi < 4; mi++)
        #pragma unroll
        for (int ni = 0; ni < 4; ni++)
            #pragma unroll
            for (int j = 0; j < 4; j++) acc[mi][ni][j] = 0.f;

    fill_stage(sb, Ag, tileM, tileN, 0, tid);                      CP_COMMIT();
    fill_stage(sb + STAGE_BYTES, Ag, tileM, tileN, 1, tid);        CP_COMMIT();
    fill_stage(sb + 2 * STAGE_BYTES, Ag, tileM, tileN, 2, tid);    CP_COMMIT();

    #pragma unroll 1
    for (int kc = 0; kc < NKCH; kc++) {
        if (kc < NKCH - 2)      { CP_WAIT(2); }
        else if (kc == NKCH - 2){ CP_WAIT(1); }
        else                    { CP_WAIT(0); }
        __syncthreads();
        if (kc + 3 < NKCH) {
            fill_stage(sb + (uint32_t)(((kc + 3) % NSTAGE) * STAGE_BYTES),
                       Ag, tileM, tileN, kc + 3, tid);
            CP_COMMIT();
        }
        uint32_t st = sb + (uint32_t)((kc % NSTAGE) * STAGE_BYTES);
        uint32_t aBase = st, bBase = st + A_BYTES;
        const int aRowB = warpM * 64 + (lane & 15);
        const int bRowB = warpN * 32 + ((lane >> 4) << 3) + (lane & 7);
        #pragma unroll
        for (int ks = 0; ks < 4; ks++) {
            const int u = ks * 2;
            const int aU = u + (lane >> 4);
            const int bU = u + ((lane >> 3) & 1);
            uint32_t af[4][4], bf[4][2];
            #pragma unroll
            for (int mi = 0; mi < 4; mi++)
                ldsm4(af[mi], sw_addr(aBase, aRowB + mi * 16, aU));
            #pragma unroll
            for (int nb = 0; nb < 2; nb++) {
                uint32_t r[4];
                ldsm4(r, sw_addr(bBase, bRowB + nb * 16, bU));
                bf[nb * 2 + 0][0] = r[0]; bf[nb * 2 + 0][1] = r[1];
                bf[nb * 2 + 1][0] = r[2]; bf[nb * 2 + 1][1] = r[3];
            }
            #pragma unroll
            for (int mi = 0; mi < 4; mi++)
                #pragma unroll
                for (int ni = 0; ni < 4; ni++)
                    mma16816(acc[mi][ni], af[mi], bf[ni]);
        }
    }

    // store result rows — single base pointer per CTA
    {
        float* outb = (MODE == 0) ? score_row(tileM * BM) : G_row(tileM * BM);
        #pragma unroll
        for (int mi = 0; mi < 4; mi++) {
            #pragma unroll
            for (int ni = 0; ni < 4; ni++) {
                int lr = warpM * 64 + mi * 16 + grp;
                int c0 = tileN * BN + warpN * 32 + ni * 8 + qc * 2;
                *(float2*)&outb[(size_t)lr * K_CB + c0] =
                    make_float2(acc[mi][ni][0], acc[mi][ni][1]);
                *(float2*)&outb[(size_t)(lr + 8) * K_CB + c0] =
                    make_float2(acc[mi][ni][2], acc[mi][ni][3]);
            }
        }
    }

    if (MODE == 1) return;

    __syncthreads();
    // per-tile top-2: sval[256][4] (4 warpN columns per row)
    float* sv1 = (float*)smem;                       // 4096 B
    int*   si1 = (int*)(smem + 4096);
    float* sv2 = (float*)(smem + 8192);
    int*   si2 = (int*)(smem + 12288);

    #pragma unroll
    for (int mi = 0; mi < 4; mi++) {
        Top2 lo = {-3.4e38f, 0x7fffffff, -3.4e38f, 0x7fffffff};
        Top2 hi = {-3.4e38f, 0x7fffffff, -3.4e38f, 0x7fffffff};
        #pragma unroll
        for (int ni = 0; ni < 4; ni++) {
            #pragma unroll
            for (int j = 0; j < 2; j++) {
                int c = warpN * 32 + ni * 8 + qc * 2 + j;
                t2_insert(lo, acc[mi][ni][j], c);
                t2_insert(hi, acc[mi][ni][2 + j], c);
            }
        }
        #pragma unroll
        for (int off = 1; off < 4; off <<= 1) {
            Top2 o;
            o.v1 = __shfl_xor_sync(0xffffffffu, lo.v1, off);
            o.i1 = __shfl_xor_sync(0xffffffffu, lo.i1, off);
            o.v2 = __shfl_xor_sync(0xffffffffu, lo.v2, off);
            o.i2 = __shfl_xor_sync(0xffffffffu, lo.i2, off);
            t2_merge(lo, o);
            o.v1 = __shfl_xor_sync(0xffffffffu, hi.v1, off);
            o.i1 = __shfl_xor_sync(0xffffffffu, hi.i1, off);
            o.v2 = __shfl_xor_sync(0xffffffffu, hi.v2, off);
            o.i2 = __shfl_xor_sync(0xffffffffu, hi.i2, off);
            t2_merge(hi, o);
        }
        if (qc == 0) {
            int rLo = warpM * 64 + mi * 16 + grp;
            sv1[rLo * 4 + warpN] = lo.v1;  si1[rLo * 4 + warpN] = lo.i1;
            sv2[rLo * 4 + warpN] = lo.v2;  si2[rLo * 4 + warpN] = lo.i2;
            int rHi = rLo + 8;
            sv1[rHi * 4 + warpN] = hi.v1;  si1[rHi * 4 + warpN] = hi.i1;
            sv2[rHi * 4 + warpN] = hi.v2;  si2[rHi * 4 + warpN] = hi.i2;
        }
    }
    __syncthreads();
    if (tid < 256) {
        Top2 t = {sv1[tid * 4], si1[tid * 4], sv2[tid * 4], si2[tid * 4]};
        #pragma unroll
        for (int w = 1; w < 4; w++) {   // ascending col ranges => first-max wins
            Top2 o = {sv1[tid * 4 + w], si1[tid * 4 + w],
                      sv2[tid * 4 + w], si2[tid * 4 + w]};
            t2_merge(t, o);
        }
        size_t oo = (size_t)(tileM * BM + tid) * NT + tileN;
        g_t1v[oo] = t.v1;  g_t1i[oo] = tileN * BN + t.i1;
        g_t2v[oo] = t.v2;  g_t2i[oo] = tileN * BN + t.i2;
    }
}

// ============================================================
// select step 0 / steps >= 1
// ============================================================
__global__ void select_tiles_kernel() {
    int tid = threadIdx.x, lane = tid & 31, wid = tid >> 5;
    int r = blockIdx.x * 8 + wid;
    size_t o = (size_t)r * NT + lane;
    float v1 = g_t1v[o];
    int   i1 = g_t1i[o];
    float v2 = g_t2v[o];
    #pragma unroll
    for (int off = 16; off > 0; off >>= 1) {
        float ov1 = __shfl_xor_sync(0xffffffffu, v1, off);
        int   oi1 = __shfl_xor_sync(0xffffffffu, i1, off);
        float ov2 = __shfl_xor_sync(0xffffffffu, v2, off);
        if (ov1 > v1 || (ov1 == v1 && oi1 < i1)) {
            v2 = fmaxf(ov2, v1);
            v1 = ov1; i1 = oi1;
        } else {
            v2 = fmaxf(v2, ov1);
        }
    }
    if (lane == 0) {
        g_choice[r] = i1;
        g_rowt1v[r] = v1;
        if (v1 - v2 < THR) {
            int p = atomicAdd(&g_flagcnt, 1);
            g_flaglist[p] = r;
        }
    }
}

__global__ void select_rows_kernel() {
    int r = blockIdx.x * 256 + threadIdx.x;
    if (r >= B_ROWS) return;
    g_choice[r] = g_rowt1i[r];
    if (g_rowt1v[r] - g_rowt2v[r] < THR) {
        int p = atomicAdd(&g_flagcnt, 1);
        g_flaglist[p] = r;
    }
}

// ============================================================
// refine: flagged rows, exact Kahan dots on candidates
// ============================================================
__global__ void refine_kernel(const float* __restrict__ cb) {
    __shared__ float sres[D_DIM];
    __shared__ int scand[128];
    __shared__ int scnt;
    __shared__ float sbv[8];
    __shared__ int   sbi[8];
    int tid = threadIdx.x, lane = tid & 31, wid = tid >> 5;
    int cnt = *(volatile int*)&g_flagcnt;

    for (int f = blockIdx.x; f < cnt; f += gridDim.x) {
        int r = g_flaglist[f];
        ((float4*)sres)[tid] = ((const float4*)(g_resid + (size_t)r * D_DIM))[tid];
        if (tid == 0) scnt = 0;
        __syncthreads();

        float thr = g_rowt1v[r] - THR;
        const float4* sc = (const float4*)score_row(r);
        #pragma unroll
        for (int i = 0; i < 4; i++) {
            int e = i * 256 + tid;
            float4 v = sc[e];
            int k = e * 4;
            if (v.x > thr) { int p = atomicAdd(&scnt, 1); if (p < 128) scand[p] = k; }
            if (v.y > thr) { int p = atomicAdd(&scnt, 1); if (p < 128) scand[p] = k + 1; }
            if (v.z > thr) { int p = atomicAdd(&scnt, 1); if (p < 128) scand[p] = k + 2; }
            if (v.w > thr) { int p = atomicAdd(&scnt, 1); if (p < 128) scand[p] = k + 3; }
        }
        __syncthreads();
        int nc = min(scnt, 128);

        float bv = -3.4e38f; int bi = 0x7fffffff;
        for (int c = wid; c < nc; c += 8) {
            int k = scand[c];
            const float* cbr = cb + (size_t)k * D_DIM;
            float s = 0.f, comp = 0.f;
            for (int e = lane; e < D_DIM; e += 32) {
                float prod = sres[e] * cbr[e];
                float y = prod - comp;
                float t = s + y;
                comp = (t - s) - y;
                s = t;
            }
            #pragma unroll
            for (int off = 16; off > 0; off >>= 1)
                s += __shfl_xor_sync(0xffffffffu, s, off);
            if (s > bv || (s == bv && k < bi)) { bv = s; bi = k; }
        }
        if (lane == 0) { sbv[wid] = bv; sbi[wid] = bi; }
        __syncthreads();
        if (tid == 0) {
            float v = sbv[0]; int i = sbi[0];
            #pragma unroll
            for (int w = 1; w < 8; w++)
                if (sbv[w] > v || (sbv[w] == v && sbi[w] < i)) { v = sbv[w]; i = sbi[w]; }
            g_choice[r] = i;
        }
        __syncthreads();
    }
}

// ============================================================
// fused step: gate + index write + residual update + norm +
// (if not last) score recurrence + next-step per-row top-2
// ============================================================
__global__ void step_kernel(const float* __restrict__ cb, int step, float decay,
                            int last) {
    int r = blockIdx.x;
    int tid = threadIdx.x, lane = tid & 31, wid = tid >> 5;
    __shared__ int s_idx, s_act;
    __shared__ float wsum[8];
    __shared__ float wv1[8]; __shared__ int wi1[8]; __shared__ float wv2[8];

    if (r == 0 && tid == 0) g_flagcnt = 0;

    if (tid == 0) {
        int i = g_choice[r];
        int act = g_active[r] && (sqrtf(g_norm2[r]) >= RES_TH);
        g_active[r] = act;
        g_indices[(size_t)r * L_STEPS + step] = act ? i : -1;
        s_idx = i;
        s_act = act;
    }
    __syncthreads();
    if (!s_act) return;

    int idx = s_idx;

    // --- residual update (exact fp32 chain) ---
    {
        float4* r4 = (float4*)(g_resid + (size_t)r * D_DIM);
        const float4* c4 = (const float4*)(cb + (size_t)idx * D_DIM);
        float4 v = r4[tid];
        float4 c = c4[tid];
        v.x = __fsub_rn(v.x, __fmul_rn(decay, c.x));
        v.y = __fsub_rn(v.y, __fmul_rn(decay, c.y));
        v.z = __fsub_rn(v.z, __fmul_rn(decay, c.z));
        v.w = __fsub_rn(v.w, __fmul_rn(decay, c.w));
        r4[tid] = v;
        float local = v.x * v.x + v.y * v.y + v.z * v.z + v.w * v.w;
        #pragma unroll
        for (int off = 16; off > 0; off >>= 1)
            local += __shfl_xor_sync(0xffffffffu, local, off);
        if (lane == 0) wsum[wid] = local;
    }
    __syncthreads();
    if (tid == 0) {
        float s = 0.f;
        #pragma unroll
        for (int w = 0; w < 8; w++) s += wsum[w];
        g_norm2[r] = s;
    }

    if (last) return;

    // --- score recurrence + next-step top-2 ---
    const float4* G4 = (const float4*)G_row(idx);
    float4* sc = (float4*)score_row(r);

    float v1 = -3.4e38f; int i1 = 0x7fffffff; float v2 = -3.4e38f;
    #pragma unroll
    for (int i = 0; i < 4; i++) {
        int e = i * 256 + tid;
        float4 v = sc[e];
        float4 g = G4[e];
        v.x -= decay * g.x;
        v.y -= decay * g.y;
        v.z -= decay * g.z;
        v.w -= decay * g.w;
        sc[e] = v;
        int k = e * 4;
        if (v.x > v1 || (v.x == v1 && k < i1)) { v2 = v1; v1 = v.x; i1 = k; }
        else v2 = fmaxf(v2, v.x);
        if (v.y > v1 || (v.y == v1 && k + 1 < i1)) { v2 = v1; v1 = v.y; i1 = k + 1; }
        else v2 = fmaxf(v2, v.y);
        if (v.z > v1 || (v.z == v1 && k + 2 < i1)) { v2 = v1; v1 = v.z; i1 = k + 2; }
        else v2 = fmaxf(v2, v.z);
        if (v.w > v1 || (v.w == v1 && k + 3 < i1)) { v2 = v1; v1 = v.w; i1 = k + 3; }
        else v2 = fmaxf(v2, v.w);
    }
    #pragma unroll
    for (int off = 16; off > 0; off >>= 1) {
        float ov1 = __shfl_xor_sync(0xffffffffu, v1, off);
        int   oi1 = __shfl_xor_sync(0xffffffffu, i1, off);
        float ov2 = __shfl_xor_sync(0xffffffffu, v2, off);
        if (ov1 > v1 || (ov1 == v1 && oi1 < i1)) {
            v2 = fmaxf(v1, ov2);
            v1 = ov1; i1 = oi1;
        } else {
            v2 = fmaxf(v2, ov1);
        }
    }
    if (lane == 0) { wv1[wid] = v1; wi1[wid] = i1; wv2[wid] = v2; }
    __syncthreads();
    if (tid == 0) {
        float bv1 = wv1[0]; int bi1 = wi1[0]; float bv2 = wv2[0];
        #pragma unroll
        for (int w = 1; w < 8; w++) {
            if (wv1[w] > bv1 || (wv1[w] == bv1 && wi1[w] < bi1)) {
                bv2 = fmaxf(bv1, wv2[w]);
                bv1 = wv1[w]; bi1 = wi1[w];
            } else {
                bv2 = fmaxf(bv2, wv1[w]);
            }
        }
        g_rowt1v[r] = bv1;
        g_rowt1i[r] = bi1;
        g_rowt2v[r] = bv2;
    }
}

// ============================================================
// init / split
// ============================================================
__global__ void split_cb_kernel(const float* __restrict__ cb) {
    int r = blockIdx.x;
    const float4* c4 = (const float4*)(cb + (size_t)r * D_DIM);
    __half2* h0p = (__half2*)(g_cb0 + (size_t)r * D_DIM);
    int tid = threadIdx.x;
    float4 v = c4[tid];
    h0p[tid * 2 + 0] = __float22half2_rn(make_float2(v.x, v.y));
    h0p[tid * 2 + 1] = __float22half2_rn(make_float2(v.z, v.w));
}

__global__ void init_kernel(const float* __restrict__ targets) {
    int r = blockIdx.x;
    int tid = threadIdx.x;
    int lane = tid & 31, wid = tid >> 5;
    __shared__ float wsum[8];

    const float4* t4 = (const float4*)(targets + (size_t)r * D_DIM);
    float4* r4 = (float4*)(g_resid + (size_t)r * D_DIM);
    __half2* h0p = (__half2*)(g_rh0 + (size_t)r * D_DIM);

    float4 v = t4[tid];
    r4[tid] = v;
    h0p[tid * 2 + 0] = __float22half2_rn(make_float2(v.x, v.y));
    h0p[tid * 2 + 1] = __float22half2_rn(make_float2(v.z, v.w));

    float local = v.x * v.x + v.y * v.y + v.z * v.z + v.w * v.w;
    #pragma unroll
    for (int off = 16; off > 0; off >>= 1)
        local += __shfl_xor_sync(0xffffffffu, local, off);
    if (lane == 0) wsum[wid] = local;
    __syncthreads();
    if (tid == 0) {
        float s = 0.f;
        #pragma unroll
        for (int w = 0; w < 8; w++) s += wsum[w];
        g_norm2[r] = s;
        g_active[r] = 1;
    }
}

// ============================================================
// finalize variants
// ============================================================
__global__ void out_both_f32(float* __restrict__ out) {
    int r = blockIdx.x;
    for (int c = threadIdx.x; c < D_DIM; c += 256)
        out[(size_t)B_ROWS * L_STEPS + (size_t)r * D_DIM + c] = g_resid[(size_t)r * D_DIM + c];
    if (threadIdx.x < L_STEPS)
        out[(size_t)r * L_STEPS + threadIdx.x] = (float)g_indices[(size_t)r * L_STEPS + threadIdx.x];
}
__global__ void out_idx_i32(int* __restrict__ out) {
    int i = blockIdx.x * 256 + threadIdx.x;
    if (i < B_ROWS * L_STEPS) out[i] = g_indices[i];
}
__global__ void out_res_f32(float* __restrict__ out) {
    int r = blockIdx.x;
    for (int c = threadIdx.x; c < D_DIM; c += 256)
        out[(size_t)r * D_DIM + c] = g_resid[(size_t)r * D_DIM + c];
}

// ============================================================
// host launcher
// ============================================================
extern "C" void kernel_launch(void* const* d_in, const int* in_sizes, int n_in,
                              void* d_out, int out_size) {
    const float* targets  = (const float*)d_in[0];
    const float* codebook = (const float*)d_in[1];

    cudaFuncSetAttribute(gemm_kernel<0>,
                         cudaFuncAttributeMaxDynamicSharedMemorySize, SMEM_TOTAL);
    cudaFuncSetAttribute(gemm_kernel<1>,
                         cudaFuncAttributeMaxDynamicSharedMemorySize, SMEM_TOTAL);

    split_cb_kernel<<<K_CB, 256>>>(codebook);
    init_kernel<<<B_ROWS, 256>>>(targets);

    {   // Gram matrix G = cb @ cb^T (fp32 out, 1-plane fp16)
        dim3 grid(K_CB / BM, K_CB / BN);
        gemm_kernel<1><<<grid, 512, SMEM_TOTAL>>>();
    }
    {   // initial scores = targets @ cb^T + per-tile top-2
        dim3 grid(B_ROWS / BM, K_CB / BN);
        gemm_kernel<0><<<grid, 512, SMEM_TOTAL>>>();
    }

    for (int s = 0; s < L_STEPS; s++) {
        if (s == 0) select_tiles_kernel<<<B_ROWS / 8, 256>>>();
        else        select_rows_kernel<<<B_ROWS / 256, 256>>>();
        refine_kernel<<<128, 256>>>(codebook);
        float decay = (float)pow(0.9, (double)s);
        step_kernel<<<B_ROWS, 256>>>(codebook, s, decay, s + 1 == L_STEPS);
    }

    if (out_size == B_ROWS * L_STEPS) {
        out_idx_i32<<<(B_ROWS * L_STEPS + 255) / 256, 256>>>((int*)d_out);
    } else if (out_size == B_ROWS * D_DIM) {
        out_res_f32<<<B_ROWS, 256>>>((float*)d_out);
    } else {
        out_both_f32<<<B_ROWS, 256>>>((float*)d_out);
    }
}